// round 2
// baseline (speedup 1.0000x reference)
#include <cuda_runtime.h>
#include <math.h>

// ---------------- problem constants (fixed dataset instance) ----------------
constexpr int NN = 100000;   // nodes
constexpr int EE = 1600000;  // edges
constexpr int CC = 25000;    // clusters
constexpr int GG = 64;       // graphs
constexpr int HH = 128;      // hidden / feature dim

// ---------------- zero-region layout (32-bit words) ----------------
constexpr int OFF_DEGN    = 0;
constexpr int OFF_CNTC    = OFF_DEGN + NN;          // 100000
constexpr int OFF_DEGP    = OFF_CNTC + CC;          // 125000
constexpr int OFF_BATCHP  = OFF_DEGP + CC;          // 150000
constexpr int OFF_CNTPG   = OFF_BATCHP + CC;        // 175000
constexpr int OFF_HPSUM   = OFF_CNTPG + GG;         // 175064 (16B aligned)
constexpr int OFF_POSTSUM = OFF_HPSUM + CC * HH;    // 3375064
constexpr int OFF_POSTMAX = OFF_POSTSUM + GG * HH;  // 3383256
constexpr int ZTOT        = OFF_POSTMAX + GG * HH;  // 3391448
static_assert(OFF_HPSUM % 4 == 0, "hpsum must be float4-aligned");
static_assert(OFF_POSTSUM % 4 == 0, "postsum must be float4-aligned");
static_assert(OFF_POSTMAX % 4 == 0, "postmax must be float4-aligned");

// ---------------- device scratch (static: no allocations allowed) ----------------
__device__ __align__(16) unsigned int g_zbuf[ZTOT];
__device__ __align__(16) float g_h0[(size_t)NN * HH];
__device__ __align__(16) float g_h [(size_t)NN * HH];
__device__ __align__(16) float g_hp [CC * HH];
__device__ __align__(16) float g_hw [CC * HH];
__device__ __align__(16) float g_agg[CC * HH];
__device__ int   g_srci[EE], g_dsti[EE], g_srcp[EE], g_dstp[EE];
__device__ float g_norm1[EE], g_normp[EE];
__device__ int   g_clus[NN], g_batch[NN];
__device__ float g_disN[NN], g_disP[CC];
__device__ float g_z[GG * 512];
__device__ int   g_is64;

#define P_DEGN    ((int*)  (g_zbuf + OFF_DEGN))
#define P_CNTC    ((int*)  (g_zbuf + OFF_CNTC))
#define P_DEGP    ((int*)  (g_zbuf + OFF_DEGP))
#define P_BATCHP  ((int*)  (g_zbuf + OFF_BATCHP))
#define P_CNTPG   ((int*)  (g_zbuf + OFF_CNTPG))
#define P_HPSUM   ((float*)(g_zbuf + OFF_HPSUM))
#define P_POSTSUM ((float*)(g_zbuf + OFF_POSTSUM))
#define P_POSTMAX ((float*)(g_zbuf + OFF_POSTMAX))

// vectorized float reduction (sm_90+): 4 floats per L2 atomic op
__device__ __forceinline__ void red_add_v4(float* addr, float4 v) {
    asm volatile("red.global.add.v4.f32 [%0], {%1,%2,%3,%4};"
                 :: "l"(addr), "f"(v.x), "f"(v.y), "f"(v.z), "f"(v.w)
                 : "memory");
}

// dtype-robust integer read (int64 vs int32, see g_is64 detection)
__device__ __forceinline__ long long readi(const void* p, long long i, int is64) {
    return is64 ? ((const long long*)p)[i] : (long long)((const int*)p)[i];
}

// ---------------- kernels ----------------

__global__ void k_zero() {
    for (int i = blockIdx.x * blockDim.x + threadIdx.x; i < ZTOT;
         i += gridDim.x * blockDim.x)
        g_zbuf[i] = 0u;
}

// Detect whether index arrays are int64 or int32. If the data is int32 and we
// read it as int64, entries combine two int32s -> values >= 2^32 almost surely.
__global__ void k_detect(const void* ei) {
    if (threadIdx.x == 0 && blockIdx.x == 0) {
        const long long* q = (const long long*)ei;
        int ok = 1;
        for (int i = 0; i < 64; i++) {
            long long v = q[i];
            if (v < 0 || v >= (long long)NN) { ok = 0; break; }
        }
        g_is64 = ok;
    }
}

__global__ void k_prep_edges(const void* __restrict__ ei, int E) {
    int e = blockIdx.x * blockDim.x + threadIdx.x;
    if (e >= E) return;
    int is64 = g_is64;
    int s = (int)readi(ei, e, is64);
    int d = (int)readi(ei, (long long)E + e, is64);
    g_srci[e] = s;
    g_dsti[e] = d;
    atomicAdd(&P_DEGN[d], 1);
}

__global__ void k_prep_nodes(const void* __restrict__ cl, const void* __restrict__ ba, int N) {
    int n = blockIdx.x * blockDim.x + threadIdx.x;
    if (n >= N) return;
    int is64 = g_is64;
    g_clus[n]  = (int)readi(cl, n, is64);
    g_batch[n] = (int)readi(ba, n, is64);
}

__global__ void k_disN(int N) {
    int n = blockIdx.x * blockDim.x + threadIdx.x;
    if (n >= N) return;
    g_disN[n] = rsqrtf((float)P_DEGN[n] + 1.0f);
}

// per-edge norm for conv1 + pooled edge endpoints + pooled in-degree
__global__ void k_edge2(int E) {
    int e = blockIdx.x * blockDim.x + threadIdx.x;
    if (e >= E) return;
    int s = g_srci[e], d = g_dsti[e];
    g_norm1[e] = g_disN[s] * g_disN[d];
    int sp = g_clus[s], dp = g_clus[d];
    g_srcp[e] = sp;
    g_dstp[e] = dp;
    atomicAdd(&P_DEGP[dp], 1);
}

__global__ void k_normp(int E) {
    int e = blockIdx.x * blockDim.x + threadIdx.x;
    if (e >= E) return;
    g_normp[e] = g_disP[g_srcp[e]] * g_disP[g_dstp[e]];
}

// Out[M,128] = A[M,128] @ W[128,128].  W + 16 A-rows in smem, 4x4 register tile.
__global__ void k_gemm128(const float* __restrict__ A, const float* __restrict__ W,
                          float* __restrict__ Out, int M) {
    extern __shared__ float sm[];
    float* Wsm = sm;            // 128*128 floats
    float* xs  = sm + 16384;    // 16 rows * 129 (padded)
    int t = threadIdx.x;        // 128 threads
    {
        float4* dptr = (float4*)Wsm;
        const float4* sptr = (const float4*)W;
        for (int i = t; i < 4096; i += 128) dptr[i] = sptr[i];
    }
    __syncthreads();
    int cg = t & 31;   // column group (cols cg, cg+32, cg+64, cg+96)
    int rg = t >> 5;   // row group   (rows rg*4 .. rg*4+3 of chunk)
    int row0 = blockIdx.x * 64;
    for (int chunk = 0; chunk < 64; chunk += 16) {
        int rbase = row0 + chunk;
        if (rbase >= M) return;  // uniform per block
        __syncthreads();
        for (int i = t; i < 512; i += 128) {   // 16 rows * 32 float4
            int r = i >> 5, c4 = i & 31;
            int gr = rbase + r;
            float4 v = (gr < M) ? ((const float4*)(A + (size_t)gr * 128))[c4]
                                : make_float4(0.f, 0.f, 0.f, 0.f);
            float* dd = xs + r * 129 + c4 * 4;
            dd[0] = v.x; dd[1] = v.y; dd[2] = v.z; dd[3] = v.w;
        }
        __syncthreads();
        float acc[4][4] = {};
#pragma unroll 2
        for (int k = 0; k < 128; k++) {
            float xv[4], wv[4];
#pragma unroll
            for (int r = 0; r < 4; r++) xv[r] = xs[(rg * 4 + r) * 129 + k];
#pragma unroll
            for (int c = 0; c < 4; c++) wv[c] = Wsm[k * 128 + cg + 32 * c];
#pragma unroll
            for (int r = 0; r < 4; r++)
#pragma unroll
                for (int c = 0; c < 4; c++) acc[r][c] += xv[r] * wv[c];
        }
#pragma unroll
        for (int r = 0; r < 4; r++) {
            int gr = rbase + rg * 4 + r;
            if (gr < M) {
#pragma unroll
                for (int c = 0; c < 4; c++)
                    Out[(size_t)gr * 128 + cg + 32 * c] = acc[r][c];
            }
        }
    }
}

// out[row] = in[row] * dis[row]^2  (GCN self-loop term init)
__global__ void k_self_init(const float* __restrict__ in, float* __restrict__ out,
                            const float* __restrict__ dis, int M) {
    int w = (blockIdx.x * blockDim.x + threadIdx.x) >> 5;
    int lane = threadIdx.x & 31;
    if (w >= M) return;
    float d = dis[w];
    float d2 = d * d;
    float4 v = ((const float4*)(in + (size_t)w * HH))[lane];
    v.x *= d2; v.y *= d2; v.z *= d2; v.w *= d2;
    ((float4*)(out + (size_t)w * HH))[lane] = v;
}

// agg[dst] += h[src] * norm   (one warp per edge, vectorized L2 reduction)
__global__ void k_edge_agg(const float* __restrict__ hsrc, float* __restrict__ agg,
                           const int* __restrict__ src, const int* __restrict__ dst,
                           const float* __restrict__ nrm, int E) {
    int w = (blockIdx.x * blockDim.x + threadIdx.x) >> 5;
    int lane = threadIdx.x & 31;
    if (w >= E) return;
    int s = src[w], d = dst[w];
    float nv = nrm[w];
    float4 v = ((const float4*)(hsrc + (size_t)s * HH))[lane];
    v.x *= nv; v.y *= nv; v.z *= nv; v.w *= nv;
    red_add_v4(agg + (size_t)d * HH + lane * 4, v);
}

// conv1 finalize: h = relu(agg + b1), fused with cluster pooling accumulators
__global__ void k_finalize1(const float* __restrict__ b, int N) {
    int w = (blockIdx.x * blockDim.x + threadIdx.x) >> 5;
    int lane = threadIdx.x & 31;
    if (w >= N) return;
    float4 bv = ((const float4*)b)[lane];
    float4 a = ((float4*)(g_h + (size_t)w * HH))[lane];
    a.x = fmaxf(a.x + bv.x, 0.f);
    a.y = fmaxf(a.y + bv.y, 0.f);
    a.z = fmaxf(a.z + bv.z, 0.f);
    a.w = fmaxf(a.w + bv.w, 0.f);
    ((float4*)(g_h + (size_t)w * HH))[lane] = a;
    int c = g_clus[w];
    red_add_v4(P_HPSUM + (size_t)c * HH + lane * 4, a);
    if (lane == 0) {
        atomicAdd(&P_CNTC[c], 1);
        atomicMax(&P_BATCHP[c], g_batch[w]);
    }
}

// pre-pool mean/max over sorted batch (one block per graph, binary search range)
__global__ void k_prepool(int N) {
    int g = blockIdx.x;
    int j = threadIdx.x;  // 128
    int lo = 0, hi = N;
    while (lo < hi) { int m = (lo + hi) >> 1; if (g_batch[m] < g) lo = m + 1; else hi = m; }
    int s = lo;
    lo = s; hi = N;
    while (lo < hi) { int m = (lo + hi) >> 1; if (g_batch[m] < g + 1) lo = m + 1; else hi = m; }
    int e = lo;
    float sum = 0.f, mx = 0.f;  // relu output >= 0, so 0-init max matches where(cnt>0,...)
#pragma unroll 4
    for (int n = s; n < e; n++) {
        float v = g_h[(size_t)n * HH + j];
        sum += v;
        mx = fmaxf(mx, v);
    }
    int cnt = e - s;
    g_z[g * 512 + j]       = sum / (float)(cnt > 0 ? cnt : 1);
    g_z[g * 512 + 128 + j] = mx;
}

// hp = hpsum / max(cnt,1); disP; clusters-per-graph count
__global__ void k_hp_div(int C) {
    int w = (blockIdx.x * blockDim.x + threadIdx.x) >> 5;
    int lane = threadIdx.x & 31;
    if (w >= C) return;
    int cnt = P_CNTC[w];
    float sc = 1.0f / (float)(cnt > 0 ? cnt : 1);
    float4 v = ((const float4*)(P_HPSUM + (size_t)w * HH))[lane];
    v.x *= sc; v.y *= sc; v.z *= sc; v.w *= sc;
    ((float4*)(g_hp + (size_t)w * HH))[lane] = v;
    if (lane == 0) {
        g_disP[w] = rsqrtf((float)P_DEGP[w] + 1.0f);
        atomicAdd(&P_CNTPG[P_BATCHP[w]], 1);
    }
}

// generic: hp = relu(agg + b)
__global__ void k_finalize_relu(const float* __restrict__ b, int M) {
    int w = (blockIdx.x * blockDim.x + threadIdx.x) >> 5;
    int lane = threadIdx.x & 31;
    if (w >= M) return;
    float4 bv = ((const float4*)b)[lane];
    float4 a = ((const float4*)(g_agg + (size_t)w * HH))[lane];
    a.x = fmaxf(a.x + bv.x, 0.f);
    a.y = fmaxf(a.y + bv.y, 0.f);
    a.z = fmaxf(a.z + bv.z, 0.f);
    a.w = fmaxf(a.w + bv.w, 0.f);
    ((float4*)(g_hp + (size_t)w * HH))[lane] = a;
}

// conv3 finalize fused with post pooling (sum + max over batch_p)
__global__ void k_finalize_post(const float* __restrict__ b, int M) {
    int w = (blockIdx.x * blockDim.x + threadIdx.x) >> 5;
    int lane = threadIdx.x & 31;
    if (w >= M) return;
    float4 bv = ((const float4*)b)[lane];
    float4 a = ((const float4*)(g_agg + (size_t)w * HH))[lane];
    a.x = fmaxf(a.x + bv.x, 0.f);
    a.y = fmaxf(a.y + bv.y, 0.f);
    a.z = fmaxf(a.z + bv.z, 0.f);
    a.w = fmaxf(a.w + bv.w, 0.f);
    int g = P_BATCHP[w];
    red_add_v4(P_POSTSUM + (size_t)g * HH + lane * 4, a);
    int* pm = (int*)(P_POSTMAX + (size_t)g * HH + lane * 4);
    // values >= 0 after relu -> int compare == float compare; 0-init matches reference
    atomicMax(pm + 0, __float_as_int(a.x));
    atomicMax(pm + 1, __float_as_int(a.y));
    atomicMax(pm + 2, __float_as_int(a.z));
    atomicMax(pm + 3, __float_as_int(a.w));
}

// final MLP + log_softmax (one block per graph)
__global__ void k_final(const float* __restrict__ l1w, const float* __restrict__ l1b,
                        const float* __restrict__ l2w, const float* __restrict__ l2b,
                        float* __restrict__ out) {
    __shared__ float zs[512];
    __shared__ float ys[128];
    __shared__ float os[10];
    int g = blockIdx.x, j = threadIdx.x;  // 128 threads
    zs[j]       = g_z[g * 512 + j];
    zs[128 + j] = g_z[g * 512 + 128 + j];
    int cpg = P_CNTPG[g];
    zs[256 + j] = P_POSTSUM[g * HH + j] / (float)(cpg > 0 ? cpg : 1);
    zs[384 + j] = P_POSTMAX[g * HH + j];
    __syncthreads();
    float acc = l1b[j];
#pragma unroll 8
    for (int k = 0; k < 512; k++) acc += zs[k] * l1w[k * 128 + j];
    ys[j] = fmaxf(acc, 0.f);
    __syncthreads();
    if (j < 10) {
        float a = l2b[j];
#pragma unroll 8
        for (int k = 0; k < 128; k++) a += ys[k] * l2w[k * 10 + j];
        os[j] = a;
    }
    __syncthreads();
    if (j < 10) {
        float m = os[0];
#pragma unroll
        for (int i = 1; i < 10; i++) m = fmaxf(m, os[i]);
        float ssum = 0.f;
#pragma unroll
        for (int i = 0; i < 10; i++) ssum += expf(os[i] - m);
        out[g * 10 + j] = os[j] - m - logf(ssum);
    }
}

// ---------------- host launcher ----------------
extern "C" void kernel_launch(void* const* d_in, const int* in_sizes, int n_in,
                              void* d_out, int out_size) {
    const float* x   = (const float*)d_in[0];
    const void*  ei  = d_in[1];
    const void*  ba  = d_in[2];
    const void*  cl  = d_in[3];
    const float* W1  = (const float*)d_in[6];
    const float* b1  = (const float*)d_in[7];
    const float* W2  = (const float*)d_in[8];
    const float* b2  = (const float*)d_in[9];
    const float* W3  = (const float*)d_in[10];
    const float* b3  = (const float*)d_in[11];
    const float* l1w = (const float*)d_in[12];
    const float* l1b = (const float*)d_in[13];
    const float* l2w = (const float*)d_in[14];
    const float* l2b = (const float*)d_in[15];
    float* out = (float*)d_out;

    int N = in_sizes[0] / HH;
    int E = in_sizes[1] / 2;
    int C = CC;
    (void)n_in; (void)out_size;

    void* p;
    cudaGetSymbolAddress(&p, g_h0);   float* h0   = (float*)p;
    cudaGetSymbolAddress(&p, g_h);    float* hbuf = (float*)p;
    cudaGetSymbolAddress(&p, g_hp);   float* hp   = (float*)p;
    cudaGetSymbolAddress(&p, g_hw);   float* hw   = (float*)p;
    cudaGetSymbolAddress(&p, g_agg);  float* agg  = (float*)p;
    cudaGetSymbolAddress(&p, g_srci); int* srci   = (int*)p;
    cudaGetSymbolAddress(&p, g_dsti); int* dsti   = (int*)p;
    cudaGetSymbolAddress(&p, g_srcp); int* srcp   = (int*)p;
    cudaGetSymbolAddress(&p, g_dstp); int* dstp   = (int*)p;
    cudaGetSymbolAddress(&p, g_norm1); float* norm1 = (float*)p;
    cudaGetSymbolAddress(&p, g_normp); float* normp = (float*)p;
    cudaGetSymbolAddress(&p, g_disN); float* disN = (float*)p;
    cudaGetSymbolAddress(&p, g_disP); float* disP = (float*)p;

    cudaFuncSetAttribute(k_gemm128, cudaFuncAttributeMaxDynamicSharedMemorySize, 73792);

    const int T = 256;
    int ebl = (E + T - 1) / T;       // element-per-thread over E
    int nbl = (N + T - 1) / T;       // element-per-thread over N
    int nwb = (N + 7) / 8;           // warp-per-row over N (256 thr = 8 warps)
    int ewb = (E + 7) / 8;           // warp-per-edge over E
    int cwb = (C + 7) / 8;           // warp-per-row over C

    k_zero<<<2048, T>>>();
    k_detect<<<1, 1>>>(ei);
    k_prep_edges<<<ebl, T>>>(ei, E);
    k_prep_nodes<<<nbl, T>>>(cl, ba, N);
    k_disN<<<nbl, T>>>(N);
    k_edge2<<<ebl, T>>>(E);

    // ---- conv1 ----
    k_gemm128<<<(N + 63) / 64, 128, 73792>>>(x, W1, h0, N);
    k_self_init<<<nwb, T>>>(h0, hbuf, disN, N);
    k_edge_agg<<<ewb, T>>>(h0, hbuf, srci, dsti, norm1, E);
    k_finalize1<<<nwb, T>>>(b1, N);   // relu + cluster pooling accumulation

    // ---- pre pooling ----
    k_prepool<<<GG, 128>>>(N);

    // ---- cluster mean + pooled degree norm ----
    k_hp_div<<<cwb, T>>>(C);
    k_normp<<<ebl, T>>>(E);

    // ---- conv2 ----
    k_gemm128<<<(C + 63) / 64, 128, 73792>>>(hp, W2, hw, C);
    k_self_init<<<cwb, T>>>(hw, agg, disP, C);
    k_edge_agg<<<ewb, T>>>(hw, agg, srcp, dstp, normp, E);
    k_finalize_relu<<<cwb, T>>>(b2, C);

    // ---- conv3 ----
    k_gemm128<<<(C + 63) / 64, 128, 73792>>>(hp, W3, hw, C);
    k_self_init<<<cwb, T>>>(hw, agg, disP, C);
    k_edge_agg<<<ewb, T>>>(hw, agg, srcp, dstp, normp, E);
    k_finalize_post<<<cwb, T>>>(b3, C);  // relu + post pooling accumulation

    // ---- MLP head + log_softmax ----
    k_final<<<GG, 128>>>(l1w, l1b, l2w, l2b, out);
}

// round 3
// speedup vs baseline: 1.2247x; 1.2247x over previous
#include <cuda_runtime.h>
#include <math.h>

// ---------------- problem constants (fixed dataset instance) ----------------
constexpr int NN = 100000;   // nodes
constexpr int EE = 1600000;  // edges
constexpr int CC = 25000;    // clusters
constexpr int GG = 64;       // graphs
constexpr int HH = 128;      // hidden / feature dim

// ---------------- zero-region layout (32-bit words) ----------------
constexpr int OFF_DEGN    = 0;
constexpr int OFF_CNTC    = OFF_DEGN + NN;
constexpr int OFF_DEGP    = OFF_CNTC + CC;
constexpr int OFF_BATCHP  = OFF_DEGP + CC;
constexpr int OFF_CNTPG   = OFF_BATCHP + CC;
constexpr int OFF_CURN    = OFF_CNTPG + GG;
constexpr int OFF_CURC    = OFF_CURN + NN;
constexpr int OFF_HPSUM   = OFF_CURC + CC;          // stays 16B aligned (mult of 4)
constexpr int OFF_POSTSUM = OFF_HPSUM + CC * HH;
constexpr int OFF_POSTMAX = OFF_POSTSUM + GG * HH;
constexpr int ZTOT        = OFF_POSTMAX + GG * HH;
static_assert(OFF_HPSUM % 4 == 0, "hpsum must be float4-aligned");

// ---------------- device scratch (static: no allocations allowed) ----------------
__device__ __align__(16) unsigned int g_zbuf[ZTOT];
__device__ __align__(16) float g_h0[(size_t)NN * HH];
__device__ __align__(16) float g_h [(size_t)NN * HH];
__device__ __align__(16) float g_hp [CC * HH];
__device__ __align__(16) float g_hw [CC * HH];
__device__ int   g_srci[EE], g_dsti[EE], g_srcp[EE], g_dstp[EE];
__device__ int   g_ssN[EE];          // src sorted by dst (node graph)
__device__ int   g_ssP[EE];          // src_p sorted by dst_p (pooled graph)
__device__ int   g_rowptrN[NN + 1], g_rowptrC[CC + 1];
__device__ int   g_auxN[128], g_auxC[128];
__device__ int   g_clus[NN], g_batch[NN];
__device__ float g_disN[NN], g_disP[CC];
__device__ float g_z[GG * 512];
__device__ int   g_is64;

#define P_DEGN    ((int*)  (g_zbuf + OFF_DEGN))
#define P_CNTC    ((int*)  (g_zbuf + OFF_CNTC))
#define P_DEGP    ((int*)  (g_zbuf + OFF_DEGP))
#define P_BATCHP  ((int*)  (g_zbuf + OFF_BATCHP))
#define P_CNTPG   ((int*)  (g_zbuf + OFF_CNTPG))
#define P_CURN    ((int*)  (g_zbuf + OFF_CURN))
#define P_CURC    ((int*)  (g_zbuf + OFF_CURC))
#define P_HPSUM   ((float*)(g_zbuf + OFF_HPSUM))
#define P_POSTSUM ((float*)(g_zbuf + OFF_POSTSUM))
#define P_POSTMAX ((float*)(g_zbuf + OFF_POSTMAX))

// vectorized float reduction (sm_90+): 4 floats per L2 atomic op
__device__ __forceinline__ void red_add_v4(float* addr, float4 v) {
    asm volatile("red.global.add.v4.f32 [%0], {%1,%2,%3,%4};"
                 :: "l"(addr), "f"(v.x), "f"(v.y), "f"(v.z), "f"(v.w)
                 : "memory");
}

__device__ __forceinline__ long long readi(const void* p, long long i, int is64) {
    return is64 ? ((const long long*)p)[i] : (long long)((const int*)p)[i];
}

// ---------------- kernels ----------------

__global__ void k_zero() {
    for (int i = blockIdx.x * blockDim.x + threadIdx.x; i < ZTOT;
         i += gridDim.x * blockDim.x)
        g_zbuf[i] = 0u;
}

// int64 vs int32 index detection (int32 read as int64 -> values >= 2^32 a.s.)
__global__ void k_detect(const void* ei) {
    if (threadIdx.x == 0 && blockIdx.x == 0) {
        const long long* q = (const long long*)ei;
        int ok = 1;
        for (int i = 0; i < 64; i++) {
            long long v = q[i];
            if (v < 0 || v >= (long long)NN) { ok = 0; break; }
        }
        g_is64 = ok;
    }
}

__global__ void k_prep_edges(const void* __restrict__ ei, int E) {
    int e = blockIdx.x * blockDim.x + threadIdx.x;
    if (e >= E) return;
    int is64 = g_is64;
    int s = (int)readi(ei, e, is64);
    int d = (int)readi(ei, (long long)E + e, is64);
    g_srci[e] = s;
    g_dsti[e] = d;
    atomicAdd(&P_DEGN[d], 1);
}

__global__ void k_prep_nodes(const void* __restrict__ cl, const void* __restrict__ ba, int N) {
    int n = blockIdx.x * blockDim.x + threadIdx.x;
    if (n >= N) return;
    int is64 = g_is64;
    g_clus[n]  = (int)readi(cl, n, is64);
    g_batch[n] = (int)readi(ba, n, is64);
}

__global__ void k_disN(int N) {
    int n = blockIdx.x * blockDim.x + threadIdx.x;
    if (n >= N) return;
    g_disN[n] = rsqrtf((float)P_DEGN[n] + 1.0f);
}

// pooled edge endpoints + pooled in-degree
__global__ void k_edge2(int E) {
    int e = blockIdx.x * blockDim.x + threadIdx.x;
    if (e >= E) return;
    int sp = g_clus[g_srci[e]], dp = g_clus[g_dsti[e]];
    g_srcp[e] = sp;
    g_dstp[e] = dp;
    atomicAdd(&P_DEGP[dp], 1);
}

// ---- exclusive scan (1024 elems / block) ----
__global__ void k_scan_block(const int* __restrict__ in, int* __restrict__ out,
                             int* __restrict__ aux, int n) {
    __shared__ int sh[256];
    int t = threadIdx.x;
    int base = blockIdx.x * 1024 + t * 4;
    int v[4]; int s = 0;
#pragma unroll
    for (int i = 0; i < 4; i++) {
        v[i] = (base + i < n) ? in[base + i] : 0;
        s += v[i];
    }
    sh[t] = s;
    __syncthreads();
    for (int off = 1; off < 256; off <<= 1) {
        int x = (t >= off) ? sh[t - off] : 0;
        __syncthreads();
        sh[t] += x;
        __syncthreads();
    }
    int run = sh[t] - s;  // exclusive prefix of this thread
#pragma unroll
    for (int i = 0; i < 4; i++) {
        if (base + i < n) out[base + i] = run;
        run += v[i];
    }
    if (t == 255) aux[blockIdx.x] = sh[255];
}

__global__ void k_scan_aux(int* aux, int nb) {
    if (threadIdx.x == 0 && blockIdx.x == 0) {
        int run = 0;
        for (int i = 0; i < nb; i++) { int tval = aux[i]; aux[i] = run; run += tval; }
    }
}

__global__ void k_scan_add(int* __restrict__ out, const int* __restrict__ aux,
                           int n, int total) {
    int i = blockIdx.x * blockDim.x + threadIdx.x;
    if (i < n) out[i] += aux[i >> 10];
    if (i == 0) out[n] = total;
}

// bucket placement: src sorted by dst for both graphs
__global__ void k_place(int E) {
    int e = blockIdx.x * blockDim.x + threadIdx.x;
    if (e >= E) return;
    int d  = g_dsti[e];
    g_ssN[g_rowptrN[d] + atomicAdd(&P_CURN[d], 1)] = g_srci[e];
    int dp = g_dstp[e];
    g_ssP[g_rowptrC[dp] + atomicAdd(&P_CURC[dp], 1)] = g_srcp[e];
}

// Out[M,128] = A[M,128] @ W[128,128].  W + 16 A-rows in smem, 4x4 register tile.
__global__ void k_gemm128(const float* __restrict__ A, const float* __restrict__ W,
                          float* __restrict__ Out, int M) {
    extern __shared__ float sm[];
    float* Wsm = sm;            // 128*128 floats
    float* xs  = sm + 16384;    // 16 rows * 129 (padded)
    int t = threadIdx.x;        // 128 threads
    {
        float4* dptr = (float4*)Wsm;
        const float4* sptr = (const float4*)W;
        for (int i = t; i < 4096; i += 128) dptr[i] = sptr[i];
    }
    __syncthreads();
    int cg = t & 31;
    int rg = t >> 5;
    int row0 = blockIdx.x * 64;
    for (int chunk = 0; chunk < 64; chunk += 16) {
        int rbase = row0 + chunk;
        if (rbase >= M) return;
        __syncthreads();
        for (int i = t; i < 512; i += 128) {
            int r = i >> 5, c4 = i & 31;
            int gr = rbase + r;
            float4 v = (gr < M) ? ((const float4*)(A + (size_t)gr * 128))[c4]
                                : make_float4(0.f, 0.f, 0.f, 0.f);
            float* dd = xs + r * 129 + c4 * 4;
            dd[0] = v.x; dd[1] = v.y; dd[2] = v.z; dd[3] = v.w;
        }
        __syncthreads();
        float acc[4][4] = {};
#pragma unroll 2
        for (int k = 0; k < 128; k++) {
            float xv[4], wv[4];
#pragma unroll
            for (int r = 0; r < 4; r++) xv[r] = xs[(rg * 4 + r) * 129 + k];
#pragma unroll
            for (int c = 0; c < 4; c++) wv[c] = Wsm[k * 128 + cg + 32 * c];
#pragma unroll
            for (int r = 0; r < 4; r++)
#pragma unroll
                for (int c = 0; c < 4; c++) acc[r][c] += xv[r] * wv[c];
        }
#pragma unroll
        for (int r = 0; r < 4; r++) {
            int gr = rbase + rg * 4 + r;
            if (gr < M) {
#pragma unroll
                for (int c = 0; c < 4; c++)
                    Out[(size_t)gr * 128 + cg + 32 * c] = acc[r][c];
            }
        }
    }
}

// ---- CSR gather convs: one warp per dst node ----

// conv1: h = relu(self + neighbor_sum + b1), fused with cluster pooling accum
__global__ void k_conv1_gather(const float* __restrict__ hin, const float* __restrict__ b,
                               int N) {
    int n = (blockIdx.x * blockDim.x + threadIdx.x) >> 5;
    int lane = threadIdx.x & 31;
    if (n >= N) return;
    float dn = g_disN[n];
    float4 a = ((const float4*)(hin + (size_t)n * HH))[lane];
    float d2 = dn * dn;
    a.x *= d2; a.y *= d2; a.z *= d2; a.w *= d2;
    int e0 = g_rowptrN[n], e1 = g_rowptrN[n + 1];
    for (int e = e0; e < e1; e++) {
        int s = g_ssN[e];
        float nv = g_disN[s] * dn;
        float4 v = ((const float4*)(hin + (size_t)s * HH))[lane];
        a.x += v.x * nv; a.y += v.y * nv; a.z += v.z * nv; a.w += v.w * nv;
    }
    float4 bv = ((const float4*)b)[lane];
    a.x = fmaxf(a.x + bv.x, 0.f);
    a.y = fmaxf(a.y + bv.y, 0.f);
    a.z = fmaxf(a.z + bv.z, 0.f);
    a.w = fmaxf(a.w + bv.w, 0.f);
    ((float4*)(g_h + (size_t)n * HH))[lane] = a;
    int c = g_clus[n];
    red_add_v4(P_HPSUM + (size_t)c * HH + lane * 4, a);
    if (lane == 0) {
        atomicAdd(&P_CNTC[c], 1);
        atomicMax(&P_BATCHP[c], g_batch[n]);
    }
}

// pooled conv (conv2): hp_out = relu(self + neighbor_sum + b)
__global__ void k_convp_gather(const float* __restrict__ hin, const float* __restrict__ b,
                               float* __restrict__ out, int C) {
    int n = (blockIdx.x * blockDim.x + threadIdx.x) >> 5;
    int lane = threadIdx.x & 31;
    if (n >= C) return;
    float dn = g_disP[n];
    float4 a = ((const float4*)(hin + (size_t)n * HH))[lane];
    float d2 = dn * dn;
    a.x *= d2; a.y *= d2; a.z *= d2; a.w *= d2;
    int e0 = g_rowptrC[n], e1 = g_rowptrC[n + 1];
    for (int e = e0; e < e1; e++) {
        int s = g_ssP[e];
        float nv = g_disP[s] * dn;
        float4 v = ((const float4*)(hin + (size_t)s * HH))[lane];
        a.x += v.x * nv; a.y += v.y * nv; a.z += v.z * nv; a.w += v.w * nv;
    }
    float4 bv = ((const float4*)b)[lane];
    a.x = fmaxf(a.x + bv.x, 0.f);
    a.y = fmaxf(a.y + bv.y, 0.f);
    a.z = fmaxf(a.z + bv.z, 0.f);
    a.w = fmaxf(a.w + bv.w, 0.f);
    ((float4*)(out + (size_t)n * HH))[lane] = a;
}

// pooled conv (conv3): fused with post pooling (sum + max over batch_p)
__global__ void k_convp_post(const float* __restrict__ hin, const float* __restrict__ b,
                             int C) {
    int n = (blockIdx.x * blockDim.x + threadIdx.x) >> 5;
    int lane = threadIdx.x & 31;
    if (n >= C) return;
    float dn = g_disP[n];
    float4 a = ((const float4*)(hin + (size_t)n * HH))[lane];
    float d2 = dn * dn;
    a.x *= d2; a.y *= d2; a.z *= d2; a.w *= d2;
    int e0 = g_rowptrC[n], e1 = g_rowptrC[n + 1];
    for (int e = e0; e < e1; e++) {
        int s = g_ssP[e];
        float nv = g_disP[s] * dn;
        float4 v = ((const float4*)(hin + (size_t)s * HH))[lane];
        a.x += v.x * nv; a.y += v.y * nv; a.z += v.z * nv; a.w += v.w * nv;
    }
    float4 bv = ((const float4*)b)[lane];
    a.x = fmaxf(a.x + bv.x, 0.f);
    a.y = fmaxf(a.y + bv.y, 0.f);
    a.z = fmaxf(a.z + bv.z, 0.f);
    a.w = fmaxf(a.w + bv.w, 0.f);
    int g = P_BATCHP[n];
    red_add_v4(P_POSTSUM + (size_t)g * HH + lane * 4, a);
    int* pm = (int*)(P_POSTMAX + (size_t)g * HH + lane * 4);
    // post-relu values >= 0 -> int compare == float compare; 0-init matches reference
    atomicMax(pm + 0, __float_as_int(a.x));
    atomicMax(pm + 1, __float_as_int(a.y));
    atomicMax(pm + 2, __float_as_int(a.z));
    atomicMax(pm + 3, __float_as_int(a.w));
}

// pre-pool mean/max over sorted batch (one block per graph, binary search range)
__global__ void k_prepool(int N) {
    int g = blockIdx.x;
    int j = threadIdx.x;
    int lo = 0, hi = N;
    while (lo < hi) { int m = (lo + hi) >> 1; if (g_batch[m] < g) lo = m + 1; else hi = m; }
    int s = lo;
    lo = s; hi = N;
    while (lo < hi) { int m = (lo + hi) >> 1; if (g_batch[m] < g + 1) lo = m + 1; else hi = m; }
    int e = lo;
    float sum = 0.f, mx = 0.f;
#pragma unroll 4
    for (int n = s; n < e; n++) {
        float v = g_h[(size_t)n * HH + j];
        sum += v;
        mx = fmaxf(mx, v);
    }
    int cnt = e - s;
    g_z[g * 512 + j]       = sum / (float)(cnt > 0 ? cnt : 1);
    g_z[g * 512 + 128 + j] = mx;
}

// hp = hpsum / max(cnt,1); disP; clusters-per-graph count
__global__ void k_hp_div(int C) {
    int w = (blockIdx.x * blockDim.x + threadIdx.x) >> 5;
    int lane = threadIdx.x & 31;
    if (w >= C) return;
    int cnt = P_CNTC[w];
    float sc = 1.0f / (float)(cnt > 0 ? cnt : 1);
    float4 v = ((const float4*)(P_HPSUM + (size_t)w * HH))[lane];
    v.x *= sc; v.y *= sc; v.z *= sc; v.w *= sc;
    ((float4*)(g_hp + (size_t)w * HH))[lane] = v;
    if (lane == 0) {
        g_disP[w] = rsqrtf((float)P_DEGP[w] + 1.0f);
        atomicAdd(&P_CNTPG[P_BATCHP[w]], 1);
    }
}

// final MLP + log_softmax (one block per graph)
__global__ void k_final(const float* __restrict__ l1w, const float* __restrict__ l1b,
                        const float* __restrict__ l2w, const float* __restrict__ l2b,
                        float* __restrict__ out) {
    __shared__ float zs[512];
    __shared__ float ys[128];
    __shared__ float os[10];
    int g = blockIdx.x, j = threadIdx.x;
    zs[j]       = g_z[g * 512 + j];
    zs[128 + j] = g_z[g * 512 + 128 + j];
    int cpg = P_CNTPG[g];
    zs[256 + j] = P_POSTSUM[g * HH + j] / (float)(cpg > 0 ? cpg : 1);
    zs[384 + j] = P_POSTMAX[g * HH + j];
    __syncthreads();
    float acc = l1b[j];
#pragma unroll 8
    for (int k = 0; k < 512; k++) acc += zs[k] * l1w[k * 128 + j];
    ys[j] = fmaxf(acc, 0.f);
    __syncthreads();
    if (j < 10) {
        float a = l2b[j];
#pragma unroll 8
        for (int k = 0; k < 128; k++) a += ys[k] * l2w[k * 10 + j];
        os[j] = a;
    }
    __syncthreads();
    if (j < 10) {
        float m = os[0];
#pragma unroll
        for (int i = 1; i < 10; i++) m = fmaxf(m, os[i]);
        float ssum = 0.f;
#pragma unroll
        for (int i = 0; i < 10; i++) ssum += expf(os[i] - m);
        out[g * 10 + j] = os[j] - m - logf(ssum);
    }
}

// ---------------- host launcher ----------------
extern "C" void kernel_launch(void* const* d_in, const int* in_sizes, int n_in,
                              void* d_out, int out_size) {
    const float* x   = (const float*)d_in[0];
    const void*  ei  = d_in[1];
    const void*  ba  = d_in[2];
    const void*  cl  = d_in[3];
    const float* W1  = (const float*)d_in[6];
    const float* b1  = (const float*)d_in[7];
    const float* W2  = (const float*)d_in[8];
    const float* b2  = (const float*)d_in[9];
    const float* W3  = (const float*)d_in[10];
    const float* b3  = (const float*)d_in[11];
    const float* l1w = (const float*)d_in[12];
    const float* l1b = (const float*)d_in[13];
    const float* l2w = (const float*)d_in[14];
    const float* l2b = (const float*)d_in[15];
    float* out = (float*)d_out;

    int N = in_sizes[0] / HH;
    int E = in_sizes[1] / 2;
    int C = CC;
    (void)n_in; (void)out_size;

    void* p;
    cudaGetSymbolAddress(&p, g_h0);      float* h0   = (float*)p;
    cudaGetSymbolAddress(&p, g_hp);      float* hp   = (float*)p;
    cudaGetSymbolAddress(&p, g_hw);      float* hw   = (float*)p;
    cudaGetSymbolAddress(&p, g_rowptrN); int* rpN    = (int*)p;
    cudaGetSymbolAddress(&p, g_rowptrC); int* rpC    = (int*)p;
    cudaGetSymbolAddress(&p, g_auxN);    int* auxN   = (int*)p;
    cudaGetSymbolAddress(&p, g_auxC);    int* auxC   = (int*)p;
    cudaGetSymbolAddress(&p, g_zbuf);    unsigned int* zb = (unsigned int*)p;
    int* degN = (int*)(zb + OFF_DEGN);
    int* degP = (int*)(zb + OFF_DEGP);

    cudaFuncSetAttribute(k_gemm128, cudaFuncAttributeMaxDynamicSharedMemorySize, 73792);

    const int T = 256;
    int ebl = (E + T - 1) / T;
    int nbl = (N + T - 1) / T;
    int nwb = (N + 7) / 8;
    int cwb = (C + 7) / 8;
    int nbN = (N + 1023) / 1024;
    int nbC = (C + 1023) / 1024;

    k_zero<<<2048, T>>>();
    k_detect<<<1, 1>>>(ei);
    k_prep_edges<<<ebl, T>>>(ei, E);
    k_prep_nodes<<<nbl, T>>>(cl, ba, N);
    k_disN<<<nbl, T>>>(N);
    k_edge2<<<ebl, T>>>(E);

    // ---- CSR build (counting sort by dst, both graphs) ----
    k_scan_block<<<nbN, 256>>>(degN, rpN, auxN, N);
    k_scan_aux<<<1, 1>>>(auxN, nbN);
    k_scan_add<<<nbl, T>>>(rpN, auxN, N, E);
    k_scan_block<<<nbC, 256>>>(degP, rpC, auxC, C);
    k_scan_aux<<<1, 1>>>(auxC, nbC);
    k_scan_add<<<(C + T - 1) / T, T>>>(rpC, auxC, C, E);
    k_place<<<ebl, T>>>(E);

    // ---- conv1 (gather) ----
    k_gemm128<<<(N + 63) / 64, 128, 73792>>>(x, W1, h0, N);
    k_conv1_gather<<<nwb, T>>>(h0, b1, N);

    // ---- pre pooling ----
    k_prepool<<<GG, 128>>>(N);

    // ---- cluster mean + pooled degree norm ----
    k_hp_div<<<cwb, T>>>(C);

    // ---- conv2 (gather) ----
    k_gemm128<<<(C + 63) / 64, 128, 73792>>>(hp, W2, hw, C);
    k_convp_gather<<<cwb, T>>>(hw, b2, hp, C);

    // ---- conv3 (gather, fused post pooling) ----
    k_gemm128<<<(C + 63) / 64, 128, 73792>>>(hp, W3, hw, C);
    k_convp_post<<<cwb, T>>>(hw, b3, C);

    // ---- MLP head + log_softmax ----
    k_final<<<GG, 128>>>(l1w, l1b, l2w, l2b, out);
}

// round 4
// speedup vs baseline: 2.2439x; 1.8322x over previous
#include <cuda_runtime.h>
#include <math.h>

// ---------------- problem constants ----------------
constexpr int NN = 100000;   // nodes
constexpr int EE = 1600000;  // edges
constexpr int CC = 25000;    // clusters
constexpr int GG = 64;       // graphs
constexpr int HH = 128;      // hidden / feature dim
constexpr int PPB = 16;      // prepool blocks per graph

// ---------------- zero-region layout (32-bit words) ----------------
constexpr int OFF_DEGN    = 0;
constexpr int OFF_CNTC    = OFF_DEGN + NN;
constexpr int OFF_DEGP    = OFF_CNTC + CC;
constexpr int OFF_BATCHP  = OFF_DEGP + CC;
constexpr int OFF_CNTPG   = OFF_BATCHP + CC;
constexpr int OFF_CURN    = OFF_CNTPG + GG;
constexpr int OFF_CURC    = OFF_CURN + NN;
constexpr int OFF_HPSUM   = OFF_CURC + CC;
constexpr int OFF_POSTSUM = OFF_HPSUM + CC * HH;
constexpr int OFF_POSTMAX = OFF_POSTSUM + GG * HH;
constexpr int OFF_PRESUM  = OFF_POSTMAX + GG * HH;
constexpr int OFF_PREMAX  = OFF_PRESUM + GG * HH;
constexpr int ZTOT        = OFF_PREMAX + GG * HH;
static_assert(OFF_HPSUM % 4 == 0, "hpsum must be float4-aligned");

// ---------------- device scratch ----------------
__device__ __align__(16) unsigned int g_zbuf[ZTOT];
__device__ __align__(16) float g_h0[(size_t)NN * HH];
__device__ __align__(16) float g_h [(size_t)NN * HH];
__device__ __align__(16) float g_hp [CC * HH];
__device__ __align__(16) float g_hw [CC * HH];
__device__ int   g_srci[EE], g_dsti[EE], g_srcp[EE], g_dstp[EE];
__device__ int2  g_ssN[EE];          // {src, bits(disN[src])} sorted by dst
__device__ int2  g_ssP[EE];          // {src_p, bits(disP[src_p])} sorted by dst_p
__device__ int   g_rowptrN[NN + 1], g_rowptrC[CC + 1];
__device__ int   g_auxN[128], g_auxC[128];
__device__ int   g_clus[NN], g_batch[NN];
__device__ float g_disN[NN], g_disP[CC];
__device__ int   g_is64;

#define P_DEGN    ((int*)  (g_zbuf + OFF_DEGN))
#define P_CNTC    ((int*)  (g_zbuf + OFF_CNTC))
#define P_DEGP    ((int*)  (g_zbuf + OFF_DEGP))
#define P_BATCHP  ((int*)  (g_zbuf + OFF_BATCHP))
#define P_CNTPG   ((int*)  (g_zbuf + OFF_CNTPG))
#define P_CURN    ((int*)  (g_zbuf + OFF_CURN))
#define P_CURC    ((int*)  (g_zbuf + OFF_CURC))
#define P_HPSUM   ((float*)(g_zbuf + OFF_HPSUM))
#define P_POSTSUM ((float*)(g_zbuf + OFF_POSTSUM))
#define P_POSTMAX ((float*)(g_zbuf + OFF_POSTMAX))
#define P_PRESUM  ((float*)(g_zbuf + OFF_PRESUM))
#define P_PREMAX  ((float*)(g_zbuf + OFF_PREMAX))

__device__ __forceinline__ void red_add_v4(float* addr, float4 v) {
    asm volatile("red.global.add.v4.f32 [%0], {%1,%2,%3,%4};"
                 :: "l"(addr), "f"(v.x), "f"(v.y), "f"(v.z), "f"(v.w)
                 : "memory");
}
__device__ __forceinline__ void red_add_f(float* addr, float v) {
    asm volatile("red.global.add.f32 [%0], %1;" :: "l"(addr), "f"(v) : "memory");
}
__device__ __forceinline__ unsigned int f2tf(float f) {
    unsigned int r;
    asm("cvt.rna.tf32.f32 %0, %1;" : "=r"(r) : "f"(f));
    return r;
}
__device__ __forceinline__ long long readi(const void* p, long long i, int is64) {
    return is64 ? ((const long long*)p)[i] : (long long)((const int*)p)[i];
}

// ---------------- kernels ----------------

__global__ void k_zero() {
    for (int i = blockIdx.x * blockDim.x + threadIdx.x; i < ZTOT;
         i += gridDim.x * blockDim.x)
        g_zbuf[i] = 0u;
}

// int64 vs int32 index detection
__global__ void k_detect(const void* ei) {
    if (threadIdx.x == 0 && blockIdx.x == 0) {
        const long long* q = (const long long*)ei;
        int ok = 1;
        for (int i = 0; i < 64; i++) {
            long long v = q[i];
            if (v < 0 || v >= (long long)NN) { ok = 0; break; }
        }
        g_is64 = ok;
    }
}

__global__ void k_prep_nodes(const void* __restrict__ cl, const void* __restrict__ ba, int N) {
    int n = blockIdx.x * blockDim.x + threadIdx.x;
    if (n >= N) return;
    int is64 = g_is64;
    g_clus[n]  = (int)readi(cl, n, is64);
    g_batch[n] = (int)readi(ba, n, is64);
}

// edge endpoints (both graphs) + in-degrees
__global__ void k_prep_edges(const void* __restrict__ ei, int E) {
    int e = blockIdx.x * blockDim.x + threadIdx.x;
    if (e >= E) return;
    int is64 = g_is64;
    int s = (int)readi(ei, e, is64);
    int d = (int)readi(ei, (long long)E + e, is64);
    g_srci[e] = s;
    g_dsti[e] = d;
    atomicAdd(&P_DEGN[d], 1);
    int sp = g_clus[s], dp = g_clus[d];
    g_srcp[e] = sp;
    g_dstp[e] = dp;
    atomicAdd(&P_DEGP[dp], 1);
}

__global__ void k_dis(int N, int C) {
    int i = blockIdx.x * blockDim.x + threadIdx.x;
    if (i < N) g_disN[i] = rsqrtf((float)P_DEGN[i] + 1.0f);
    if (i < C) g_disP[i] = rsqrtf((float)P_DEGP[i] + 1.0f);
}

// ---- exclusive scan (1024 elems / block) ----
__global__ void k_scan_block(const int* __restrict__ in, int* __restrict__ out,
                             int* __restrict__ aux, int n) {
    __shared__ int sh[256];
    int t = threadIdx.x;
    int base = blockIdx.x * 1024 + t * 4;
    int v[4]; int s = 0;
#pragma unroll
    for (int i = 0; i < 4; i++) {
        v[i] = (base + i < n) ? in[base + i] : 0;
        s += v[i];
    }
    sh[t] = s;
    __syncthreads();
    for (int off = 1; off < 256; off <<= 1) {
        int x = (t >= off) ? sh[t - off] : 0;
        __syncthreads();
        sh[t] += x;
        __syncthreads();
    }
    int run = sh[t] - s;
#pragma unroll
    for (int i = 0; i < 4; i++) {
        if (base + i < n) out[base + i] = run;
        run += v[i];
    }
    if (t == 255) aux[blockIdx.x] = sh[255];
}

__global__ void k_scan_aux(int* aux, int nb) {
    if (threadIdx.x == 0 && blockIdx.x == 0) {
        int run = 0;
        for (int i = 0; i < nb; i++) { int tval = aux[i]; aux[i] = run; run += tval; }
    }
}

__global__ void k_scan_add(int* __restrict__ out, const int* __restrict__ aux,
                           int n, int total) {
    int i = blockIdx.x * blockDim.x + threadIdx.x;
    if (i < n) out[i] += aux[i >> 10];
    if (i == 0) out[n] = total;
}

// bucket placement: {src, dis[src]} sorted by dst, both graphs
__global__ void k_place(int E) {
    int e = blockIdx.x * blockDim.x + threadIdx.x;
    if (e >= E) return;
    int s = g_srci[e];
    int d = g_dsti[e];
    int2 rec; rec.x = s; rec.y = __float_as_int(g_disN[s]);
    g_ssN[g_rowptrN[d] + atomicAdd(&P_CURN[d], 1)] = rec;
    int sp = g_srcp[e];
    int dp = g_dstp[e];
    int2 recp; recp.x = sp; recp.y = __float_as_int(g_disP[sp]);
    g_ssP[g_rowptrC[dp] + atomicAdd(&P_CURC[dp], 1)] = recp;
}

// ---- TF32 tensor-core GEMM: Out[M,128] = A[M,128] @ W[128,128] ----
// block: 256 thr = 8 warps; block tile 128x128; warp tile 32(M) x 64(N)
__global__ void k_gemm_tc(const float* __restrict__ A, const float* __restrict__ W,
                          float* __restrict__ Out, int M) {
    __shared__ unsigned int As[128][36];   // 32 k-cols, pad 36
    __shared__ unsigned int Ws[32][136];   // 128 n-cols, pad 136
    int t = threadIdx.x;
    int wid = t >> 5, lane = t & 31;
    int grp = lane >> 2, thr = lane & 3;
    int wm = (wid & 3) * 32;         // warp row base within tile
    int wn = (wid >> 2) * 64;        // warp col base
    int row0 = blockIdx.x * 128;

    float c[2][8][4];
#pragma unroll
    for (int m = 0; m < 2; m++)
#pragma unroll
        for (int n = 0; n < 8; n++)
#pragma unroll
            for (int i = 0; i < 4; i++) c[m][n][i] = 0.f;

    for (int kc = 0; kc < 4; kc++) {
        // stage A chunk: rows row0..row0+127, cols kc*32..+31
        {
            int idx = t;                        // 1024 float4 / 256 thr = 4 each
#pragma unroll
            for (int r4 = 0; r4 < 4; r4++, idx += 256) {
                int row = idx >> 3, c4 = idx & 7;
                int gr = row0 + row;
                float4 v = (gr < M)
                    ? ((const float4*)(A + (size_t)gr * 128 + kc * 32))[c4]
                    : make_float4(0.f, 0.f, 0.f, 0.f);
                As[row][c4 * 4 + 0] = f2tf(v.x);
                As[row][c4 * 4 + 1] = f2tf(v.y);
                As[row][c4 * 4 + 2] = f2tf(v.z);
                As[row][c4 * 4 + 3] = f2tf(v.w);
            }
        }
        // stage W chunk: rows (k) kc*32..+31, all 128 cols
        {
            int idx = t;
#pragma unroll
            for (int r4 = 0; r4 < 4; r4++, idx += 256) {
                int kr = idx >> 5, c4 = idx & 31;
                float4 v = ((const float4*)(W + (size_t)(kc * 32 + kr) * 128))[c4];
                Ws[kr][c4 * 4 + 0] = f2tf(v.x);
                Ws[kr][c4 * 4 + 1] = f2tf(v.y);
                Ws[kr][c4 * 4 + 2] = f2tf(v.z);
                Ws[kr][c4 * 4 + 3] = f2tf(v.w);
            }
        }
        __syncthreads();
#pragma unroll
        for (int ks = 0; ks < 4; ks++) {
            int k0 = ks * 8;
            unsigned int a[2][4];
#pragma unroll
            for (int m = 0; m < 2; m++) {
                int rb = wm + m * 16;
                a[m][0] = As[rb + grp    ][k0 + thr    ];
                a[m][1] = As[rb + grp + 8][k0 + thr    ];
                a[m][2] = As[rb + grp    ][k0 + thr + 4];
                a[m][3] = As[rb + grp + 8][k0 + thr + 4];
            }
#pragma unroll
            for (int nt = 0; nt < 8; nt++) {
                int n0 = wn + nt * 8;
                unsigned int b0 = Ws[k0 + thr    ][n0 + grp];
                unsigned int b1 = Ws[k0 + thr + 4][n0 + grp];
#pragma unroll
                for (int m = 0; m < 2; m++) {
                    asm volatile(
                        "mma.sync.aligned.m16n8k8.row.col.f32.tf32.tf32.f32 "
                        "{%0,%1,%2,%3}, {%4,%5,%6,%7}, {%8,%9}, {%0,%1,%2,%3};"
                        : "+f"(c[m][nt][0]), "+f"(c[m][nt][1]),
                          "+f"(c[m][nt][2]), "+f"(c[m][nt][3])
                        : "r"(a[m][0]), "r"(a[m][1]), "r"(a[m][2]), "r"(a[m][3]),
                          "r"(b0), "r"(b1));
                }
            }
        }
        __syncthreads();
    }
    // epilogue
#pragma unroll
    for (int m = 0; m < 2; m++) {
#pragma unroll
        for (int nt = 0; nt < 8; nt++) {
            int col = wn + nt * 8 + thr * 2;
            int gr0 = row0 + wm + m * 16 + grp;
            if (gr0 < M) {
                float2 v = make_float2(c[m][nt][0], c[m][nt][1]);
                *(float2*)(Out + (size_t)gr0 * 128 + col) = v;
            }
            int gr1 = gr0 + 8;
            if (gr1 < M) {
                float2 v = make_float2(c[m][nt][2], c[m][nt][3]);
                *(float2*)(Out + (size_t)gr1 * 128 + col) = v;
            }
        }
    }
}

// ---- CSR gather convs: one warp per dst node ----

// conv1: h = relu(self + neighbor_sum + b1), fused with cluster pooling accum
__global__ void k_conv1_gather(const float* __restrict__ hin, const float* __restrict__ b,
                               int N) {
    int n = (blockIdx.x * blockDim.x + threadIdx.x) >> 5;
    int lane = threadIdx.x & 31;
    if (n >= N) return;
    float dn = g_disN[n];
    float4 a = ((const float4*)(hin + (size_t)n * HH))[lane];
    float d2 = dn * dn;
    a.x *= d2; a.y *= d2; a.z *= d2; a.w *= d2;
    int e0 = g_rowptrN[n], e1 = g_rowptrN[n + 1];
    for (int e = e0; e < e1; e++) {
        int2 sv = g_ssN[e];
        float nv = __int_as_float(sv.y) * dn;
        float4 v = ((const float4*)(hin + (size_t)sv.x * HH))[lane];
        a.x += v.x * nv; a.y += v.y * nv; a.z += v.z * nv; a.w += v.w * nv;
    }
    float4 bv = ((const float4*)b)[lane];
    a.x = fmaxf(a.x + bv.x, 0.f);
    a.y = fmaxf(a.y + bv.y, 0.f);
    a.z = fmaxf(a.z + bv.z, 0.f);
    a.w = fmaxf(a.w + bv.w, 0.f);
    ((float4*)(g_h + (size_t)n * HH))[lane] = a;
    int c = g_clus[n];
    red_add_v4(P_HPSUM + (size_t)c * HH + lane * 4, a);
    if (lane == 0) {
        atomicAdd(&P_CNTC[c], 1);
        atomicMax(&P_BATCHP[c], g_batch[n]);
    }
}

// pooled conv (conv2): out = relu(self + neighbor_sum + b)
__global__ void k_convp_gather(const float* __restrict__ hin, const float* __restrict__ b,
                               float* __restrict__ out, int C) {
    int n = (blockIdx.x * blockDim.x + threadIdx.x) >> 5;
    int lane = threadIdx.x & 31;
    if (n >= C) return;
    float dn = g_disP[n];
    float4 a = ((const float4*)(hin + (size_t)n * HH))[lane];
    float d2 = dn * dn;
    a.x *= d2; a.y *= d2; a.z *= d2; a.w *= d2;
    int e0 = g_rowptrC[n], e1 = g_rowptrC[n + 1];
    for (int e = e0; e < e1; e++) {
        int2 sv = g_ssP[e];
        float nv = __int_as_float(sv.y) * dn;
        float4 v = ((const float4*)(hin + (size_t)sv.x * HH))[lane];
        a.x += v.x * nv; a.y += v.y * nv; a.z += v.z * nv; a.w += v.w * nv;
    }
    float4 bv = ((const float4*)b)[lane];
    a.x = fmaxf(a.x + bv.x, 0.f);
    a.y = fmaxf(a.y + bv.y, 0.f);
    a.z = fmaxf(a.z + bv.z, 0.f);
    a.w = fmaxf(a.w + bv.w, 0.f);
    ((float4*)(out + (size_t)n * HH))[lane] = a;
}

// pooled conv (conv3): fused with post pooling (sum + max over batch_p)
__global__ void k_convp_post(const float* __restrict__ hin, const float* __restrict__ b,
                             int C) {
    int n = (blockIdx.x * blockDim.x + threadIdx.x) >> 5;
    int lane = threadIdx.x & 31;
    if (n >= C) return;
    float dn = g_disP[n];
    float4 a = ((const float4*)(hin + (size_t)n * HH))[lane];
    float d2 = dn * dn;
    a.x *= d2; a.y *= d2; a.z *= d2; a.w *= d2;
    int e0 = g_rowptrC[n], e1 = g_rowptrC[n + 1];
    for (int e = e0; e < e1; e++) {
        int2 sv = g_ssP[e];
        float nv = __int_as_float(sv.y) * dn;
        float4 v = ((const float4*)(hin + (size_t)sv.x * HH))[lane];
        a.x += v.x * nv; a.y += v.y * nv; a.z += v.z * nv; a.w += v.w * nv;
    }
    float4 bv = ((const float4*)b)[lane];
    a.x = fmaxf(a.x + bv.x, 0.f);
    a.y = fmaxf(a.y + bv.y, 0.f);
    a.z = fmaxf(a.z + bv.z, 0.f);
    a.w = fmaxf(a.w + bv.w, 0.f);
    int g = P_BATCHP[n];
    red_add_v4(P_POSTSUM + (size_t)g * HH + lane * 4, a);
    int* pm = (int*)(P_POSTMAX + (size_t)g * HH + lane * 4);
    atomicMax(pm + 0, __float_as_int(a.x));
    atomicMax(pm + 1, __float_as_int(a.y));
    atomicMax(pm + 2, __float_as_int(a.z));
    atomicMax(pm + 3, __float_as_int(a.w));
}

// pre-pool partial mean/max (PPB blocks per graph; atomically combined)
__global__ void k_prepool(int N) {
    int g = blockIdx.x / PPB;
    int chunk = blockIdx.x % PPB;
    int j = threadIdx.x;  // 128
    int lo = 0, hi = N;
    while (lo < hi) { int m = (lo + hi) >> 1; if (g_batch[m] < g) lo = m + 1; else hi = m; }
    int s = lo;
    lo = s; hi = N;
    while (lo < hi) { int m = (lo + hi) >> 1; if (g_batch[m] < g + 1) lo = m + 1; else hi = m; }
    int e = lo;
    int len = e - s;
    int c0 = s + (int)((long long)len * chunk / PPB);
    int c1 = s + (int)((long long)len * (chunk + 1) / PPB);
    float sum = 0.f, mx = 0.f;
#pragma unroll 8
    for (int n = c0; n < c1; n++) {
        float v = g_h[(size_t)n * HH + j];
        sum += v;
        mx = fmaxf(mx, v);
    }
    if (c1 > c0) {
        red_add_f(P_PRESUM + g * HH + j, sum);
        atomicMax((int*)(P_PREMAX + g * HH + j), __float_as_int(mx));
    }
}

// hp = hpsum / max(cnt,1); clusters-per-graph count
__global__ void k_hp_div(int C) {
    int w = (blockIdx.x * blockDim.x + threadIdx.x) >> 5;
    int lane = threadIdx.x & 31;
    if (w >= C) return;
    int cnt = P_CNTC[w];
    float sc = 1.0f / (float)(cnt > 0 ? cnt : 1);
    float4 v = ((const float4*)(P_HPSUM + (size_t)w * HH))[lane];
    v.x *= sc; v.y *= sc; v.z *= sc; v.w *= sc;
    ((float4*)(g_hp + (size_t)w * HH))[lane] = v;
    if (lane == 0) atomicAdd(&P_CNTPG[P_BATCHP[w]], 1);
}

// final MLP + log_softmax (one block per graph)
__global__ void k_final(const float* __restrict__ l1w, const float* __restrict__ l1b,
                        const float* __restrict__ l2w, const float* __restrict__ l2b,
                        float* __restrict__ out, int N) {
    __shared__ float zs[512];
    __shared__ float ys[128];
    __shared__ float os[10];
    int g = blockIdx.x, j = threadIdx.x;
    // node count of graph g (sorted batch -> binary search)
    int lo = 0, hi = N;
    while (lo < hi) { int m = (lo + hi) >> 1; if (g_batch[m] < g) lo = m + 1; else hi = m; }
    int s = lo;
    lo = s; hi = N;
    while (lo < hi) { int m = (lo + hi) >> 1; if (g_batch[m] < g + 1) lo = m + 1; else hi = m; }
    int cntN = lo - s;
    int cpg = P_CNTPG[g];
    zs[j]       = P_PRESUM[g * HH + j] / (float)(cntN > 0 ? cntN : 1);
    zs[128 + j] = P_PREMAX[g * HH + j];
    zs[256 + j] = P_POSTSUM[g * HH + j] / (float)(cpg > 0 ? cpg : 1);
    zs[384 + j] = P_POSTMAX[g * HH + j];
    __syncthreads();
    float acc = l1b[j];
#pragma unroll 8
    for (int k = 0; k < 512; k++) acc += zs[k] * l1w[k * 128 + j];
    ys[j] = fmaxf(acc, 0.f);
    __syncthreads();
    if (j < 10) {
        float a = l2b[j];
#pragma unroll 8
        for (int k = 0; k < 128; k++) a += ys[k] * l2w[k * 10 + j];
        os[j] = a;
    }
    __syncthreads();
    if (j < 10) {
        float m = os[0];
#pragma unroll
        for (int i = 1; i < 10; i++) m = fmaxf(m, os[i]);
        float ssum = 0.f;
#pragma unroll
        for (int i = 0; i < 10; i++) ssum += expf(os[i] - m);
        out[g * 10 + j] = os[j] - m - logf(ssum);
    }
}

// ---------------- host launcher ----------------
extern "C" void kernel_launch(void* const* d_in, const int* in_sizes, int n_in,
                              void* d_out, int out_size) {
    const float* x   = (const float*)d_in[0];
    const void*  ei  = d_in[1];
    const void*  ba  = d_in[2];
    const void*  cl  = d_in[3];
    const float* W1  = (const float*)d_in[6];
    const float* b1  = (const float*)d_in[7];
    const float* W2  = (const float*)d_in[8];
    const float* b2  = (const float*)d_in[9];
    const float* W3  = (const float*)d_in[10];
    const float* b3  = (const float*)d_in[11];
    const float* l1w = (const float*)d_in[12];
    const float* l1b = (const float*)d_in[13];
    const float* l2w = (const float*)d_in[14];
    const float* l2b = (const float*)d_in[15];
    float* out = (float*)d_out;

    int N = in_sizes[0] / HH;
    int E = in_sizes[1] / 2;
    int C = CC;
    (void)n_in; (void)out_size;

    void* p;
    cudaGetSymbolAddress(&p, g_h0);      float* h0 = (float*)p;
    cudaGetSymbolAddress(&p, g_hp);      float* hp = (float*)p;
    cudaGetSymbolAddress(&p, g_hw);      float* hw = (float*)p;
    cudaGetSymbolAddress(&p, g_rowptrN); int* rpN  = (int*)p;
    cudaGetSymbolAddress(&p, g_rowptrC); int* rpC  = (int*)p;
    cudaGetSymbolAddress(&p, g_auxN);    int* auxN = (int*)p;
    cudaGetSymbolAddress(&p, g_auxC);    int* auxC = (int*)p;
    cudaGetSymbolAddress(&p, g_zbuf);    unsigned int* zb = (unsigned int*)p;
    int* degN = (int*)(zb + OFF_DEGN);
    int* degP = (int*)(zb + OFF_DEGP);

    const int T = 256;
    int ebl = (E + T - 1) / T;
    int nbl = (N + T - 1) / T;
    int nwb = (N + 7) / 8;
    int cwb = (C + 7) / 8;
    int nbN = (N + 1023) / 1024;
    int nbC = (C + 1023) / 1024;

    k_zero<<<2048, T>>>();
    k_detect<<<1, 1>>>(ei);
    k_prep_nodes<<<nbl, T>>>(cl, ba, N);
    k_prep_edges<<<ebl, T>>>(ei, E);
    k_dis<<<nbl, T>>>(N, C);

    // CSR build (counting sort by dst, both graphs)
    k_scan_block<<<nbN, 256>>>(degN, rpN, auxN, N);
    k_scan_aux<<<1, 1>>>(auxN, nbN);
    k_scan_add<<<nbl, T>>>(rpN, auxN, N, E);
    k_scan_block<<<nbC, 256>>>(degP, rpC, auxC, C);
    k_scan_aux<<<1, 1>>>(auxC, nbC);
    k_scan_add<<<(C + T - 1) / T, T>>>(rpC, auxC, C, E);
    k_place<<<ebl, T>>>(E);

    // conv1
    k_gemm_tc<<<(N + 127) / 128, 256>>>(x, W1, h0, N);
    k_conv1_gather<<<nwb, T>>>(h0, b1, N);

    // pre pooling
    k_prepool<<<GG * PPB, 128>>>(N);

    // cluster mean
    k_hp_div<<<cwb, T>>>(C);

    // conv2
    k_gemm_tc<<<(C + 127) / 128, 256>>>(hp, W2, hw, C);
    k_convp_gather<<<cwb, T>>>(hw, b2, hp, C);

    // conv3 (fused post pooling)
    k_gemm_tc<<<(C + 127) / 128, 256>>>(hp, W3, hw, C);
    k_convp_post<<<cwb, T>>>(hw, b3, C);

    // MLP head + log_softmax
    k_final<<<GG, 128>>>(l1w, l1b, l2w, l2b, out, N);
}

// round 5
// speedup vs baseline: 2.3765x; 1.0591x over previous
#include <cuda_runtime.h>
#include <cuda_fp16.h>
#include <math.h>

// ---------------- problem constants ----------------
constexpr int NN = 100000;   // nodes
constexpr int EE = 1600000;  // edges
constexpr int CC = 25000;    // clusters
constexpr int GG = 64;       // graphs
constexpr int HH = 128;      // hidden / feature dim
constexpr int PPB = 16;      // prepool blocks per graph

// ---------------- zero-region layout (32-bit words) ----------------
constexpr int OFF_DEGN    = 0;
constexpr int OFF_CNTC    = OFF_DEGN + NN;
constexpr int OFF_DEGP    = OFF_CNTC + CC;
constexpr int OFF_CNTPG   = OFF_DEGP + CC;
constexpr int OFF_CURN    = OFF_CNTPG + GG;
constexpr int OFF_CURC    = OFF_CURN + NN;
constexpr int OFF_CURCL   = OFF_CURC + CC;
constexpr int OFF_POSTSUM = OFF_CURCL + CC;
constexpr int OFF_POSTMAX = OFF_POSTSUM + GG * HH;
constexpr int OFF_PRESUM  = OFF_POSTMAX + GG * HH;
constexpr int OFF_PREMAX  = OFF_PRESUM + GG * HH;
constexpr int ZTOT        = OFF_PREMAX + GG * HH;
static_assert(OFF_POSTSUM % 4 == 0, "postsum must be float4-aligned");

// ---------------- device scratch ----------------
__device__ __align__(16) unsigned int g_zbuf[ZTOT];
__device__ __align__(16) __half g_h0h[(size_t)NN * HH];  // conv1 gemm out (fp16)
__device__ __align__(16) __half g_hh [(size_t)NN * HH];  // conv1 out (fp16)
__device__ __align__(16) __half g_hw [CC * HH];          // pooled gemm out (fp16)
__device__ __align__(16) float g_hp  [CC * HH];          // cluster means (fp32)
__device__ __align__(16) float g_hp2 [CC * HH];          // conv2 out (fp32)
__device__ int   g_srci[EE], g_dsti[EE], g_srcp[EE], g_dstp[EE];
__device__ int2  g_ssN[EE];          // {src, bits(disN[src])} sorted by dst
__device__ int2  g_ssP[EE];          // {src_p, bits(disP[src_p])} sorted by dst_p
__device__ int   g_memb[NN];         // node ids sorted by cluster
__device__ int   g_rowptrN[NN + 1], g_rowptrC[CC + 1], g_rowptrCL[CC + 1];
__device__ int   g_auxN[128], g_auxC[128], g_auxCL[128];
__device__ int   g_clus[NN], g_batch[NN], g_batchp[CC];
__device__ float g_disN[NN], g_disP[CC];
__device__ int   g_is64;

#define P_DEGN    ((int*)  (g_zbuf + OFF_DEGN))
#define P_CNTC    ((int*)  (g_zbuf + OFF_CNTC))
#define P_DEGP    ((int*)  (g_zbuf + OFF_DEGP))
#define P_CNTPG   ((int*)  (g_zbuf + OFF_CNTPG))
#define P_CURN    ((int*)  (g_zbuf + OFF_CURN))
#define P_CURC    ((int*)  (g_zbuf + OFF_CURC))
#define P_CURCL   ((int*)  (g_zbuf + OFF_CURCL))
#define P_POSTSUM ((float*)(g_zbuf + OFF_POSTSUM))
#define P_POSTMAX ((float*)(g_zbuf + OFF_POSTMAX))
#define P_PRESUM  ((float*)(g_zbuf + OFF_PRESUM))
#define P_PREMAX  ((float*)(g_zbuf + OFF_PREMAX))

__device__ __forceinline__ void red_add_v4(float* addr, float4 v) {
    asm volatile("red.global.add.v4.f32 [%0], {%1,%2,%3,%4};"
                 :: "l"(addr), "f"(v.x), "f"(v.y), "f"(v.z), "f"(v.w)
                 : "memory");
}
__device__ __forceinline__ void red_add_f(float* addr, float v) {
    asm volatile("red.global.add.f32 [%0], %1;" :: "l"(addr), "f"(v) : "memory");
}
__device__ __forceinline__ unsigned int f2tf(float f) {
    unsigned int r;
    asm("cvt.rna.tf32.f32 %0, %1;" : "=r"(r) : "f"(f));
    return r;
}
__device__ __forceinline__ long long readi(const void* p, long long i, int is64) {
    return is64 ? ((const long long*)p)[i] : (long long)((const int*)p)[i];
}
// 4 halfs (uint2) -> float4
__device__ __forceinline__ float4 h4f(uint2 r) {
    __half2 a = *(__half2*)&r.x;
    __half2 b = *(__half2*)&r.y;
    float2 fa = __half22float2(a), fb = __half22float2(b);
    return make_float4(fa.x, fa.y, fb.x, fb.y);
}
// float4 -> 4 halfs (uint2)
__device__ __forceinline__ uint2 f4h(float4 v) {
    __half2 a = __float22half2_rn(make_float2(v.x, v.y));
    __half2 b = __float22half2_rn(make_float2(v.z, v.w));
    uint2 r; r.x = *(unsigned int*)&a; r.y = *(unsigned int*)&b;
    return r;
}

// ---------------- kernels ----------------

__global__ void k_zero() {
    for (int i = blockIdx.x * blockDim.x + threadIdx.x; i < ZTOT;
         i += gridDim.x * blockDim.x)
        g_zbuf[i] = 0u;
}

__global__ void k_detect(const void* ei) {
    if (threadIdx.x == 0 && blockIdx.x == 0) {
        const long long* q = (const long long*)ei;
        int ok = 1;
        for (int i = 0; i < 64; i++) {
            long long v = q[i];
            if (v < 0 || v >= (long long)NN) { ok = 0; break; }
        }
        g_is64 = ok;
    }
}

__global__ void k_prep_nodes(const void* __restrict__ cl, const void* __restrict__ ba, int N) {
    int n = blockIdx.x * blockDim.x + threadIdx.x;
    if (n >= N) return;
    int is64 = g_is64;
    int c = (int)readi(cl, n, is64);
    g_clus[n]  = c;
    g_batch[n] = (int)readi(ba, n, is64);
    atomicAdd(&P_CNTC[c], 1);
}

__global__ void k_prep_edges(const void* __restrict__ ei, int E) {
    int e = blockIdx.x * blockDim.x + threadIdx.x;
    if (e >= E) return;
    int is64 = g_is64;
    int s = (int)readi(ei, e, is64);
    int d = (int)readi(ei, (long long)E + e, is64);
    g_srci[e] = s;
    g_dsti[e] = d;
    atomicAdd(&P_DEGN[d], 1);
    int sp = g_clus[s], dp = g_clus[d];
    g_srcp[e] = sp;
    g_dstp[e] = dp;
    atomicAdd(&P_DEGP[dp], 1);
}

__global__ void k_dis(int N, int C) {
    int i = blockIdx.x * blockDim.x + threadIdx.x;
    if (i < N) g_disN[i] = rsqrtf((float)P_DEGN[i] + 1.0f);
    if (i < C) g_disP[i] = rsqrtf((float)P_DEGP[i] + 1.0f);
}

// ---- exclusive scan (1024 elems / block) ----
__global__ void k_scan_block(const int* __restrict__ in, int* __restrict__ out,
                             int* __restrict__ aux, int n) {
    __shared__ int sh[256];
    int t = threadIdx.x;
    int base = blockIdx.x * 1024 + t * 4;
    int v[4]; int s = 0;
#pragma unroll
    for (int i = 0; i < 4; i++) {
        v[i] = (base + i < n) ? in[base + i] : 0;
        s += v[i];
    }
    sh[t] = s;
    __syncthreads();
    for (int off = 1; off < 256; off <<= 1) {
        int x = (t >= off) ? sh[t - off] : 0;
        __syncthreads();
        sh[t] += x;
        __syncthreads();
    }
    int run = sh[t] - s;
#pragma unroll
    for (int i = 0; i < 4; i++) {
        if (base + i < n) out[base + i] = run;
        run += v[i];
    }
    if (t == 255) aux[blockIdx.x] = sh[255];
}

__global__ void k_scan_aux(int* aux, int nb) {
    if (threadIdx.x == 0 && blockIdx.x == 0) {
        int run = 0;
        for (int i = 0; i < nb; i++) { int tval = aux[i]; aux[i] = run; run += tval; }
    }
}

__global__ void k_scan_add(int* __restrict__ out, const int* __restrict__ aux,
                           int n, int total) {
    int i = blockIdx.x * blockDim.x + threadIdx.x;
    if (i < n) out[i] += aux[i >> 10];
    if (i == 0) out[n] = total;
}

// bucket placement: {src, dis[src]} sorted by dst, both graphs
__global__ void k_place(int E) {
    int e = blockIdx.x * blockDim.x + threadIdx.x;
    if (e >= E) return;
    int s = g_srci[e];
    int d = g_dsti[e];
    int2 rec; rec.x = s; rec.y = __float_as_int(g_disN[s]);
    g_ssN[g_rowptrN[d] + atomicAdd(&P_CURN[d], 1)] = rec;
    int sp = g_srcp[e];
    int dp = g_dstp[e];
    int2 recp; recp.x = sp; recp.y = __float_as_int(g_disP[sp]);
    g_ssP[g_rowptrC[dp] + atomicAdd(&P_CURC[dp], 1)] = recp;
}

// node -> cluster membership buckets
__global__ void k_place_nodes(int N) {
    int n = blockIdx.x * blockDim.x + threadIdx.x;
    if (n >= N) return;
    int c = g_clus[n];
    g_memb[g_rowptrCL[c] + atomicAdd(&P_CURCL[c], 1)] = n;
}

// ---- TF32 tensor-core GEMM: Out[M,128] = A[M,128] @ W[128,128] ----
// fp32 A/W, fp16 or fp32 Out. block 256 thr; tile 128x128; warp 32x64.
template <typename OutT>
__global__ void k_gemm_tc(const float* __restrict__ A, const float* __restrict__ W,
                          OutT* __restrict__ Out, int M) {
    __shared__ unsigned int As[128][36];
    __shared__ unsigned int Ws[32][136];
    int t = threadIdx.x;
    int wid = t >> 5, lane = t & 31;
    int grp = lane >> 2, thr = lane & 3;
    int wm = (wid & 3) * 32;
    int wn = (wid >> 2) * 64;
    int row0 = blockIdx.x * 128;

    float c[2][8][4];
#pragma unroll
    for (int m = 0; m < 2; m++)
#pragma unroll
        for (int n = 0; n < 8; n++)
#pragma unroll
            for (int i = 0; i < 4; i++) c[m][n][i] = 0.f;

    for (int kc = 0; kc < 4; kc++) {
        {
            int idx = t;
#pragma unroll
            for (int r4 = 0; r4 < 4; r4++, idx += 256) {
                int row = idx >> 3, c4 = idx & 7;
                int gr = row0 + row;
                float4 v = (gr < M)
                    ? ((const float4*)(A + (size_t)gr * 128 + kc * 32))[c4]
                    : make_float4(0.f, 0.f, 0.f, 0.f);
                As[row][c4 * 4 + 0] = f2tf(v.x);
                As[row][c4 * 4 + 1] = f2tf(v.y);
                As[row][c4 * 4 + 2] = f2tf(v.z);
                As[row][c4 * 4 + 3] = f2tf(v.w);
            }
        }
        {
            int idx = t;
#pragma unroll
            for (int r4 = 0; r4 < 4; r4++, idx += 256) {
                int kr = idx >> 5, c4 = idx & 31;
                float4 v = ((const float4*)(W + (size_t)(kc * 32 + kr) * 128))[c4];
                Ws[kr][c4 * 4 + 0] = f2tf(v.x);
                Ws[kr][c4 * 4 + 1] = f2tf(v.y);
                Ws[kr][c4 * 4 + 2] = f2tf(v.z);
                Ws[kr][c4 * 4 + 3] = f2tf(v.w);
            }
        }
        __syncthreads();
#pragma unroll
        for (int ks = 0; ks < 4; ks++) {
            int k0 = ks * 8;
            unsigned int a[2][4];
#pragma unroll
            for (int m = 0; m < 2; m++) {
                int rb = wm + m * 16;
                a[m][0] = As[rb + grp    ][k0 + thr    ];
                a[m][1] = As[rb + grp + 8][k0 + thr    ];
                a[m][2] = As[rb + grp    ][k0 + thr + 4];
                a[m][3] = As[rb + grp + 8][k0 + thr + 4];
            }
#pragma unroll
            for (int nt = 0; nt < 8; nt++) {
                int n0 = wn + nt * 8;
                unsigned int b0 = Ws[k0 + thr    ][n0 + grp];
                unsigned int b1 = Ws[k0 + thr + 4][n0 + grp];
#pragma unroll
                for (int m = 0; m < 2; m++) {
                    asm volatile(
                        "mma.sync.aligned.m16n8k8.row.col.f32.tf32.tf32.f32 "
                        "{%0,%1,%2,%3}, {%4,%5,%6,%7}, {%8,%9}, {%0,%1,%2,%3};"
                        : "+f"(c[m][nt][0]), "+f"(c[m][nt][1]),
                          "+f"(c[m][nt][2]), "+f"(c[m][nt][3])
                        : "r"(a[m][0]), "r"(a[m][1]), "r"(a[m][2]), "r"(a[m][3]),
                          "r"(b0), "r"(b1));
                }
            }
        }
        __syncthreads();
    }
#pragma unroll
    for (int m = 0; m < 2; m++) {
#pragma unroll
        for (int nt = 0; nt < 8; nt++) {
            int col = wn + nt * 8 + thr * 2;
            int gr0 = row0 + wm + m * 16 + grp;
            int gr1 = gr0 + 8;
            if constexpr (sizeof(OutT) == 2) {
                if (gr0 < M) {
                    __half2 v = __float22half2_rn(make_float2(c[m][nt][0], c[m][nt][1]));
                    *(__half2*)((__half*)Out + (size_t)gr0 * 128 + col) = v;
                }
                if (gr1 < M) {
                    __half2 v = __float22half2_rn(make_float2(c[m][nt][2], c[m][nt][3]));
                    *(__half2*)((__half*)Out + (size_t)gr1 * 128 + col) = v;
                }
            } else {
                if (gr0 < M)
                    *(float2*)((float*)Out + (size_t)gr0 * 128 + col) =
                        make_float2(c[m][nt][0], c[m][nt][1]);
                if (gr1 < M)
                    *(float2*)((float*)Out + (size_t)gr1 * 128 + col) =
                        make_float2(c[m][nt][2], c[m][nt][3]);
            }
        }
    }
}

// ---- CSR gather convs (fp16 features): one warp per dst row ----

// conv1: h = relu(self + neighbor_sum + b1)  (fp16 in, fp16 out, no atomics)
__global__ void k_conv1_gather(const __half* __restrict__ hin, const float* __restrict__ b,
                               __half* __restrict__ hout, int N) {
    int n = (blockIdx.x * blockDim.x + threadIdx.x) >> 5;
    int lane = threadIdx.x & 31;
    if (n >= N) return;
    float dn = g_disN[n];
    float4 a = h4f(((const uint2*)(hin + (size_t)n * HH))[lane]);
    float d2 = dn * dn;
    a.x *= d2; a.y *= d2; a.z *= d2; a.w *= d2;
    int e0 = g_rowptrN[n], e1 = g_rowptrN[n + 1];
    for (int e = e0; e < e1; e++) {
        int2 sv = g_ssN[e];
        float nv = __int_as_float(sv.y) * dn;
        float4 v = h4f(((const uint2*)(hin + (size_t)sv.x * HH))[lane]);
        a.x += v.x * nv; a.y += v.y * nv; a.z += v.z * nv; a.w += v.w * nv;
    }
    float4 bv = ((const float4*)b)[lane];
    a.x = fmaxf(a.x + bv.x, 0.f);
    a.y = fmaxf(a.y + bv.y, 0.f);
    a.z = fmaxf(a.z + bv.z, 0.f);
    a.w = fmaxf(a.w + bv.w, 0.f);
    ((uint2*)(hout + (size_t)n * HH))[lane] = f4h(a);
}

// cluster mean pooling via membership CSR: hp[c] = mean(h[members]); batch_p; CNTPG
__global__ void k_hp(const __half* __restrict__ h, float* __restrict__ hp, int C) {
    int c = (blockIdx.x * blockDim.x + threadIdx.x) >> 5;
    int lane = threadIdx.x & 31;
    if (c >= C) return;
    int m0 = g_rowptrCL[c], m1 = g_rowptrCL[c + 1];
    float4 a = make_float4(0.f, 0.f, 0.f, 0.f);
    int bmax = 0;
    for (int i = m0; i < m1; i++) {
        int node = g_memb[i];
        bmax = max(bmax, g_batch[node]);
        float4 v = h4f(((const uint2*)(h + (size_t)node * HH))[lane]);
        a.x += v.x; a.y += v.y; a.z += v.z; a.w += v.w;
    }
    int cnt = m1 - m0;
    float sc = 1.0f / (float)(cnt > 0 ? cnt : 1);
    a.x *= sc; a.y *= sc; a.z *= sc; a.w *= sc;
    ((float4*)(hp + (size_t)c * HH))[lane] = a;
    if (lane == 0) {
        g_batchp[c] = bmax;
        atomicAdd(&P_CNTPG[bmax], 1);
    }
}

// pooled conv2: out = relu(self + neighbor_sum + b)  (fp16 in, fp32 out)
__global__ void k_convp_gather(const __half* __restrict__ hin, const float* __restrict__ b,
                               float* __restrict__ out, int C) {
    int n = (blockIdx.x * blockDim.x + threadIdx.x) >> 5;
    int lane = threadIdx.x & 31;
    if (n >= C) return;
    float dn = g_disP[n];
    float4 a = h4f(((const uint2*)(hin + (size_t)n * HH))[lane]);
    float d2 = dn * dn;
    a.x *= d2; a.y *= d2; a.z *= d2; a.w *= d2;
    int e0 = g_rowptrC[n], e1 = g_rowptrC[n + 1];
    for (int e = e0; e < e1; e++) {
        int2 sv = g_ssP[e];
        float nv = __int_as_float(sv.y) * dn;
        float4 v = h4f(((const uint2*)(hin + (size_t)sv.x * HH))[lane]);
        a.x += v.x * nv; a.y += v.y * nv; a.z += v.z * nv; a.w += v.w * nv;
    }
    float4 bv = ((const float4*)b)[lane];
    a.x = fmaxf(a.x + bv.x, 0.f);
    a.y = fmaxf(a.y + bv.y, 0.f);
    a.z = fmaxf(a.z + bv.z, 0.f);
    a.w = fmaxf(a.w + bv.w, 0.f);
    ((float4*)(out + (size_t)n * HH))[lane] = a;
}

// pooled conv3: fused with post pooling (sum + max over batch_p)
__global__ void k_convp_post(const __half* __restrict__ hin, const float* __restrict__ b,
                             int C) {
    int n = (blockIdx.x * blockDim.x + threadIdx.x) >> 5;
    int lane = threadIdx.x & 31;
    if (n >= C) return;
    float dn = g_disP[n];
    float4 a = h4f(((const uint2*)(hin + (size_t)n * HH))[lane]);
    float d2 = dn * dn;
    a.x *= d2; a.y *= d2; a.z *= d2; a.w *= d2;
    int e0 = g_rowptrC[n], e1 = g_rowptrC[n + 1];
    for (int e = e0; e < e1; e++) {
        int2 sv = g_ssP[e];
        float nv = __int_as_float(sv.y) * dn;
        float4 v = h4f(((const uint2*)(hin + (size_t)sv.x * HH))[lane]);
        a.x += v.x * nv; a.y += v.y * nv; a.z += v.z * nv; a.w += v.w * nv;
    }
    float4 bv = ((const float4*)b)[lane];
    a.x = fmaxf(a.x + bv.x, 0.f);
    a.y = fmaxf(a.y + bv.y, 0.f);
    a.z = fmaxf(a.z + bv.z, 0.f);
    a.w = fmaxf(a.w + bv.w, 0.f);
    int g = g_batchp[n];
    red_add_v4(P_POSTSUM + (size_t)g * HH + lane * 4, a);
    int* pm = (int*)(P_POSTMAX + (size_t)g * HH + lane * 4);
    atomicMax(pm + 0, __float_as_int(a.x));
    atomicMax(pm + 1, __float_as_int(a.y));
    atomicMax(pm + 2, __float_as_int(a.z));
    atomicMax(pm + 3, __float_as_int(a.w));
}

// pre-pool partial mean/max over fp16 h (PPB blocks per graph)
__global__ void k_prepool(const __half* __restrict__ h, int N) {
    int g = blockIdx.x / PPB;
    int chunk = blockIdx.x % PPB;
    int j = threadIdx.x;  // 128
    int lo = 0, hi = N;
    while (lo < hi) { int m = (lo + hi) >> 1; if (g_batch[m] < g) lo = m + 1; else hi = m; }
    int s = lo;
    lo = s; hi = N;
    while (lo < hi) { int m = (lo + hi) >> 1; if (g_batch[m] < g + 1) lo = m + 1; else hi = m; }
    int e = lo;
    int len = e - s;
    int c0 = s + (int)((long long)len * chunk / PPB);
    int c1 = s + (int)((long long)len * (chunk + 1) / PPB);
    float sum = 0.f, mx = 0.f;
#pragma unroll 8
    for (int n = c0; n < c1; n++) {
        float v = __half2float(h[(size_t)n * HH + j]);
        sum += v;
        mx = fmaxf(mx, v);
    }
    if (c1 > c0) {
        red_add_f(P_PRESUM + g * HH + j, sum);
        atomicMax((int*)(P_PREMAX + g * HH + j), __float_as_int(mx));
    }
}

// final MLP + log_softmax (one block per graph)
__global__ void k_final(const float* __restrict__ l1w, const float* __restrict__ l1b,
                        const float* __restrict__ l2w, const float* __restrict__ l2b,
                        float* __restrict__ out, int N) {
    __shared__ float zs[512];
    __shared__ float ys[128];
    __shared__ float os[10];
    int g = blockIdx.x, j = threadIdx.x;
    int lo = 0, hi = N;
    while (lo < hi) { int m = (lo + hi) >> 1; if (g_batch[m] < g) lo = m + 1; else hi = m; }
    int s = lo;
    lo = s; hi = N;
    while (lo < hi) { int m = (lo + hi) >> 1; if (g_batch[m] < g + 1) lo = m + 1; else hi = m; }
    int cntN = lo - s;
    int cpg = P_CNTPG[g];
    zs[j]       = P_PRESUM[g * HH + j] / (float)(cntN > 0 ? cntN : 1);
    zs[128 + j] = P_PREMAX[g * HH + j];
    zs[256 + j] = P_POSTSUM[g * HH + j] / (float)(cpg > 0 ? cpg : 1);
    zs[384 + j] = P_POSTMAX[g * HH + j];
    __syncthreads();
    float acc = l1b[j];
#pragma unroll 8
    for (int k = 0; k < 512; k++) acc += zs[k] * l1w[k * 128 + j];
    ys[j] = fmaxf(acc, 0.f);
    __syncthreads();
    if (j < 10) {
        float a = l2b[j];
#pragma unroll 8
        for (int k = 0; k < 128; k++) a += ys[k] * l2w[k * 10 + j];
        os[j] = a;
    }
    __syncthreads();
    if (j < 10) {
        float m = os[0];
#pragma unroll
        for (int i = 1; i < 10; i++) m = fmaxf(m, os[i]);
        float ssum = 0.f;
#pragma unroll
        for (int i = 0; i < 10; i++) ssum += expf(os[i] - m);
        out[g * 10 + j] = os[j] - m - logf(ssum);
    }
}

// ---------------- host launcher ----------------
extern "C" void kernel_launch(void* const* d_in, const int* in_sizes, int n_in,
                              void* d_out, int out_size) {
    const float* x   = (const float*)d_in[0];
    const void*  ei  = d_in[1];
    const void*  ba  = d_in[2];
    const void*  cl  = d_in[3];
    const float* W1  = (const float*)d_in[6];
    const float* b1  = (const float*)d_in[7];
    const float* W2  = (const float*)d_in[8];
    const float* b2  = (const float*)d_in[9];
    const float* W3  = (const float*)d_in[10];
    const float* b3  = (const float*)d_in[11];
    const float* l1w = (const float*)d_in[12];
    const float* l1b = (const float*)d_in[13];
    const float* l2w = (const float*)d_in[14];
    const float* l2b = (const float*)d_in[15];
    float* out = (float*)d_out;

    int N = in_sizes[0] / HH;
    int E = in_sizes[1] / 2;
    int C = CC;
    (void)n_in; (void)out_size;

    void* p;
    cudaGetSymbolAddress(&p, g_h0h);      __half* h0h = (__half*)p;
    cudaGetSymbolAddress(&p, g_hh);       __half* hh  = (__half*)p;
    cudaGetSymbolAddress(&p, g_hw);       __half* hw  = (__half*)p;
    cudaGetSymbolAddress(&p, g_hp);       float* hp   = (float*)p;
    cudaGetSymbolAddress(&p, g_hp2);      float* hp2  = (float*)p;
    cudaGetSymbolAddress(&p, g_rowptrN);  int* rpN    = (int*)p;
    cudaGetSymbolAddress(&p, g_rowptrC);  int* rpC    = (int*)p;
    cudaGetSymbolAddress(&p, g_rowptrCL); int* rpCL   = (int*)p;
    cudaGetSymbolAddress(&p, g_auxN);     int* auxN   = (int*)p;
    cudaGetSymbolAddress(&p, g_auxC);     int* auxC   = (int*)p;
    cudaGetSymbolAddress(&p, g_auxCL);    int* auxCL  = (int*)p;
    cudaGetSymbolAddress(&p, g_zbuf);     unsigned int* zb = (unsigned int*)p;
    int* degN = (int*)(zb + OFF_DEGN);
    int* degP = (int*)(zb + OFF_DEGP);
    int* cntC = (int*)(zb + OFF_CNTC);

    const int T = 256;
    int ebl = (E + T - 1) / T;
    int nbl = (N + T - 1) / T;
    int cbl = (C + T - 1) / T;
    int nwb = (N + 7) / 8;
    int cwb = (C + 7) / 8;
    int nbN = (N + 1023) / 1024;
    int nbC = (C + 1023) / 1024;

    k_zero<<<512, T>>>();
    k_detect<<<1, 1>>>(ei);
    k_prep_nodes<<<nbl, T>>>(cl, ba, N);
    k_prep_edges<<<ebl, T>>>(ei, E);
    k_dis<<<nbl, T>>>(N, C);

    // CSR builds: edges-by-dst (node + pooled) and nodes-by-cluster
    k_scan_block<<<nbN, 256>>>(degN, rpN, auxN, N);
    k_scan_aux<<<1, 1>>>(auxN, nbN);
    k_scan_add<<<nbl, T>>>(rpN, auxN, N, E);
    k_scan_block<<<nbC, 256>>>(degP, rpC, auxC, C);
    k_scan_aux<<<1, 1>>>(auxC, nbC);
    k_scan_add<<<cbl, T>>>(rpC, auxC, C, E);
    k_scan_block<<<nbC, 256>>>(cntC, rpCL, auxCL, C);
    k_scan_aux<<<1, 1>>>(auxCL, nbC);
    k_scan_add<<<cbl, T>>>(rpCL, auxCL, C, N);
    k_place<<<ebl, T>>>(E);
    k_place_nodes<<<nbl, T>>>(N);

    // conv1
    k_gemm_tc<__half><<<(N + 127) / 128, 256>>>(x, W1, h0h, N);
    k_conv1_gather<<<nwb, T>>>(h0h, b1, hh, N);

    // pre pooling + cluster mean (batch_p, CNTPG)
    k_prepool<<<GG * PPB, 128>>>(hh, N);
    k_hp<<<cwb, T>>>(hh, hp, C);

    // conv2
    k_gemm_tc<__half><<<(C + 127) / 128, 256>>>(hp, W2, hw, C);
    k_convp_gather<<<cwb, T>>>(hw, b2, hp2, C);

    // conv3 (fused post pooling)
    k_gemm_tc<__half><<<(C + 127) / 128, 256>>>(hp2, W3, hw, C);
    k_convp_post<<<cwb, T>>>(hw, b3, C);

    // MLP head + log_softmax
    k_final<<<GG, 128>>>(l1w, l1b, l2w, l2b, out, N);
}

// round 7
// speedup vs baseline: 2.4812x; 1.0440x over previous
#include <cuda_runtime.h>
#include <cuda_fp16.h>
#include <math.h>

// ---------------- problem constants ----------------
constexpr int NN = 100000;   // nodes
constexpr int EE = 1600000;  // edges
constexpr int CC = 25000;    // clusters
constexpr int GG = 64;       // graphs
constexpr int HH = 128;      // hidden / feature dim
constexpr int PPB = 16;      // prepool blocks per graph

// ---------------- zero-region layout (32-bit words) ----------------
constexpr int OFF_DEGN    = 0;
constexpr int OFF_CNTC    = OFF_DEGN + NN;
constexpr int OFF_DEGP    = OFF_CNTC + CC;
constexpr int OFF_CNTPG   = OFF_DEGP + CC;
constexpr int OFF_POSTSUM = OFF_CNTPG + GG;
constexpr int OFF_POSTMAX = OFF_POSTSUM + GG * HH;
constexpr int OFF_PRESUM  = OFF_POSTMAX + GG * HH;
constexpr int OFF_PREMAX  = OFF_PRESUM + GG * HH;
constexpr int ZTOT        = OFF_PREMAX + GG * HH;
static_assert(OFF_POSTSUM % 4 == 0, "postsum must be float4-aligned");

// ---------------- device scratch ----------------
__device__ __align__(16) unsigned int g_zbuf[ZTOT];
__device__ __align__(16) __half g_h0h[(size_t)NN * HH];  // conv1 gemm out (fp16)
__device__ __align__(16) __half g_hh [(size_t)NN * HH];  // conv1 out (fp16)
__device__ __align__(16) __half g_hw [CC * HH];          // pooled gemm out (fp16)
__device__ __align__(16) float g_hp  [CC * HH];          // cluster means (fp32)
__device__ __align__(16) float g_hp2 [CC * HH];          // conv2 out (fp32)
__device__ int   g_srci[EE], g_dsti[EE], g_srcp[EE], g_dstp[EE];
__device__ int2  g_ssN[EE];          // {src, bits(disN[src])} sorted by dst
__device__ int2  g_ssP[EE];          // {src_p, bits(disP[src_p])} sorted by dst_p
__device__ int   g_memb[NN];         // node ids sorted by cluster
__device__ int   g_rowptrN[NN + 1], g_rowptrC[CC + 1], g_rowptrCL[CC + 1];
__device__ int   g_auxN[128], g_auxC[128], g_auxCL[128];
__device__ int   g_clus[NN], g_batch[NN], g_batchp[CC];
__device__ float g_disN[NN], g_disP[CC];
__device__ int   g_is64;

#define P_DEGN    ((int*)  (g_zbuf + OFF_DEGN))
#define P_CNTC    ((int*)  (g_zbuf + OFF_CNTC))
#define P_DEGP    ((int*)  (g_zbuf + OFF_DEGP))
#define P_CNTPG   ((int*)  (g_zbuf + OFF_CNTPG))
#define P_POSTSUM ((float*)(g_zbuf + OFF_POSTSUM))
#define P_POSTMAX ((float*)(g_zbuf + OFF_POSTMAX))
#define P_PRESUM  ((float*)(g_zbuf + OFF_PRESUM))
#define P_PREMAX  ((float*)(g_zbuf + OFF_PREMAX))

__device__ __forceinline__ void red_add_v4(float* addr, float4 v) {
    asm volatile("red.global.add.v4.f32 [%0], {%1,%2,%3,%4};"
                 :: "l"(addr), "f"(v.x), "f"(v.y), "f"(v.z), "f"(v.w)
                 : "memory");
}
__device__ __forceinline__ void red_add_f(float* addr, float v) {
    asm volatile("red.global.add.f32 [%0], %1;" :: "l"(addr), "f"(v) : "memory");
}
__device__ __forceinline__ unsigned int f2tf(float f) {
    unsigned int r;
    asm("cvt.rna.tf32.f32 %0, %1;" : "=r"(r) : "f"(f));
    return r;
}
__device__ __forceinline__ long long readi(const void* p, long long i, int is64) {
    return is64 ? ((const long long*)p)[i] : (long long)((const int*)p)[i];
}
__device__ __forceinline__ float4 h4f(uint2 r) {
    __half2 a = *(__half2*)&r.x;
    __half2 b = *(__half2*)&r.y;
    float2 fa = __half22float2(a), fb = __half22float2(b);
    return make_float4(fa.x, fa.y, fb.x, fb.y);
}
__device__ __forceinline__ uint2 f4h(float4 v) {
    __half2 a = __float22half2_rn(make_float2(v.x, v.y));
    __half2 b = __float22half2_rn(make_float2(v.z, v.w));
    uint2 r; r.x = *(unsigned int*)&a; r.y = *(unsigned int*)&b;
    return r;
}
__device__ __forceinline__ void fma4(float4& a, float4 v, float n) {
    a.x += v.x * n; a.y += v.y * n; a.z += v.z * n; a.w += v.w * n;
}

// 4-way unrolled latency-pipelined neighbor gather:  a += sum nrm_e * hin[src_e]
__device__ __forceinline__ float4 gather_nbrs(const __half* __restrict__ hin,
                                              const int2* __restrict__ ss,
                                              int e0, int e1, float dn, int lane,
                                              float4 a) {
    int e = e0;
    for (; e + 4 <= e1; e += 4) {
        int2 s0 = ss[e], s1 = ss[e + 1], s2 = ss[e + 2], s3 = ss[e + 3];
        uint2 r0 = ((const uint2*)(hin + (size_t)s0.x * HH))[lane];
        uint2 r1 = ((const uint2*)(hin + (size_t)s1.x * HH))[lane];
        uint2 r2 = ((const uint2*)(hin + (size_t)s2.x * HH))[lane];
        uint2 r3 = ((const uint2*)(hin + (size_t)s3.x * HH))[lane];
        fma4(a, h4f(r0), __int_as_float(s0.y) * dn);
        fma4(a, h4f(r1), __int_as_float(s1.y) * dn);
        fma4(a, h4f(r2), __int_as_float(s2.y) * dn);
        fma4(a, h4f(r3), __int_as_float(s3.y) * dn);
    }
    for (; e < e1; e++) {
        int2 sv = ss[e];
        uint2 r = ((const uint2*)(hin + (size_t)sv.x * HH))[lane];
        fma4(a, h4f(r), __int_as_float(sv.y) * dn);
    }
    return a;
}

// ---------------- kernels ----------------

__global__ void k_zero(const void* ei) {
    if (blockIdx.x == 0 && threadIdx.x == 0) {
        const long long* q = (const long long*)ei;
        int ok = 1;
        for (int i = 0; i < 64; i++) {
            long long v = q[i];
            if (v < 0 || v >= (long long)NN) { ok = 0; break; }
        }
        g_is64 = ok;  // int32 reinterpreted as int64 -> huge values a.s.
    }
    for (int i = blockIdx.x * blockDim.x + threadIdx.x; i < ZTOT;
         i += gridDim.x * blockDim.x)
        g_zbuf[i] = 0u;
}

__global__ void k_prep_nodes(const void* __restrict__ cl, const void* __restrict__ ba, int N) {
    int n = blockIdx.x * blockDim.x + threadIdx.x;
    if (n >= N) return;
    int is64 = g_is64;
    int c = (int)readi(cl, n, is64);
    g_clus[n]  = c;
    g_batch[n] = (int)readi(ba, n, is64);
    atomicAdd(&P_CNTC[c], 1);
}

__global__ void k_prep_edges(const void* __restrict__ ei, int E) {
    int e = blockIdx.x * blockDim.x + threadIdx.x;
    if (e >= E) return;
    int is64 = g_is64;
    int s = (int)readi(ei, e, is64);
    int d = (int)readi(ei, (long long)E + e, is64);
    g_srci[e] = s;
    g_dsti[e] = d;
    atomicAdd(&P_DEGN[d], 1);
    int sp = g_clus[s], dp = g_clus[d];
    g_srcp[e] = sp;
    g_dstp[e] = dp;
    atomicAdd(&P_DEGP[dp], 1);
}

__global__ void k_dis(int N, int C) {
    int i = blockIdx.x * blockDim.x + threadIdx.x;
    if (i < N) g_disN[i] = rsqrtf((float)P_DEGN[i] + 1.0f);
    if (i < C) g_disP[i] = rsqrtf((float)P_DEGP[i] + 1.0f);
}

// ---- exclusive scan (1024 elems / block) ----
__global__ void k_scan_block(const int* __restrict__ in, int* __restrict__ out,
                             int* __restrict__ aux, int n) {
    __shared__ int sh[256];
    int t = threadIdx.x;
    int base = blockIdx.x * 1024 + t * 4;
    int v[4]; int s = 0;
#pragma unroll
    for (int i = 0; i < 4; i++) {
        v[i] = (base + i < n) ? in[base + i] : 0;
        s += v[i];
    }
    sh[t] = s;
    __syncthreads();
    for (int off = 1; off < 256; off <<= 1) {
        int x = (t >= off) ? sh[t - off] : 0;
        __syncthreads();
        sh[t] += x;
        __syncthreads();
    }
    int run = sh[t] - s;
#pragma unroll
    for (int i = 0; i < 4; i++) {
        if (base + i < n) out[base + i] = run;
        run += v[i];
    }
    if (t == 255) aux[blockIdx.x] = sh[255];
}

__global__ void k_scan_aux(int* aux, int nb) {
    if (threadIdx.x == 0 && blockIdx.x == 0) {
        int run = 0;
        for (int i = 0; i < nb; i++) { int tval = aux[i]; aux[i] = run; run += tval; }
    }
}

__global__ void k_scan_add(int* __restrict__ out, const int* __restrict__ aux,
                           int n, int total) {
    int i = blockIdx.x * blockDim.x + threadIdx.x;
    if (i < n) out[i] += aux[i >> 10];
    if (i == 0) out[n] = total;
}

// bucket placement with destructive rowptr cursors: after this kernel
// rowptr[d] == end(d), so row d spans [rowptr[d-1], rowptr[d]) with row0 start 0.
__global__ void k_place(int E) {
    int e = blockIdx.x * blockDim.x + threadIdx.x;
    if (e >= E) return;
    int s = g_srci[e];
    int d = g_dsti[e];
    int2 rec; rec.x = s; rec.y = __float_as_int(g_disN[s]);
    g_ssN[atomicAdd(&g_rowptrN[d], 1)] = rec;
    int sp = g_srcp[e];
    int dp = g_dstp[e];
    int2 recp; recp.x = sp; recp.y = __float_as_int(g_disP[sp]);
    g_ssP[atomicAdd(&g_rowptrC[dp], 1)] = recp;
}

__global__ void k_place_nodes(int N) {
    int n = blockIdx.x * blockDim.x + threadIdx.x;
    if (n >= N) return;
    g_memb[atomicAdd(&g_rowptrCL[g_clus[n]], 1)] = n;
}

// ---- TF32 tensor-core GEMM: Out[M,128] = A[M,128] @ W[128,128] ----
template <typename OutT>
__global__ void k_gemm_tc(const float* __restrict__ A, const float* __restrict__ W,
                          OutT* __restrict__ Out, int M) {
    __shared__ unsigned int As[128][36];
    __shared__ unsigned int Ws[32][136];
    int t = threadIdx.x;
    int wid = t >> 5, lane = t & 31;
    int grp = lane >> 2, thr = lane & 3;
    int wm = (wid & 3) * 32;
    int wn = (wid >> 2) * 64;
    int row0 = blockIdx.x * 128;

    float c[2][8][4];
#pragma unroll
    for (int m = 0; m < 2; m++)
#pragma unroll
        for (int n = 0; n < 8; n++)
#pragma unroll
            for (int i = 0; i < 4; i++) c[m][n][i] = 0.f;

    for (int kc = 0; kc < 4; kc++) {
        {
            int idx = t;
#pragma unroll
            for (int r4 = 0; r4 < 4; r4++, idx += 256) {
                int row = idx >> 3, c4 = idx & 7;
                int gr = row0 + row;
                float4 v = (gr < M)
                    ? ((const float4*)(A + (size_t)gr * 128 + kc * 32))[c4]
                    : make_float4(0.f, 0.f, 0.f, 0.f);
                As[row][c4 * 4 + 0] = f2tf(v.x);
                As[row][c4 * 4 + 1] = f2tf(v.y);
                As[row][c4 * 4 + 2] = f2tf(v.z);
                As[row][c4 * 4 + 3] = f2tf(v.w);
            }
        }
        {
            int idx = t;
#pragma unroll
            for (int r4 = 0; r4 < 4; r4++, idx += 256) {
                int kr = idx >> 5, c4 = idx & 31;
                float4 v = ((const float4*)(W + (size_t)(kc * 32 + kr) * 128))[c4];
                Ws[kr][c4 * 4 + 0] = f2tf(v.x);
                Ws[kr][c4 * 4 + 1] = f2tf(v.y);
                Ws[kr][c4 * 4 + 2] = f2tf(v.z);
                Ws[kr][c4 * 4 + 3] = f2tf(v.w);
            }
        }
        __syncthreads();
#pragma unroll
        for (int ks = 0; ks < 4; ks++) {
            int k0 = ks * 8;
            unsigned int a[2][4];
#pragma unroll
            for (int m = 0; m < 2; m++) {
                int rb = wm + m * 16;
                a[m][0] = As[rb + grp    ][k0 + thr    ];
                a[m][1] = As[rb + grp + 8][k0 + thr    ];
                a[m][2] = As[rb + grp    ][k0 + thr + 4];
                a[m][3] = As[rb + grp + 8][k0 + thr + 4];
            }
#pragma unroll
            for (int nt = 0; nt < 8; nt++) {
                int n0 = wn + nt * 8;
                unsigned int b0 = Ws[k0 + thr    ][n0 + grp];
                unsigned int b1 = Ws[k0 + thr + 4][n0 + grp];
#pragma unroll
                for (int m = 0; m < 2; m++) {
                    asm volatile(
                        "mma.sync.aligned.m16n8k8.row.col.f32.tf32.tf32.f32 "
                        "{%0,%1,%2,%3}, {%4,%5,%6,%7}, {%8,%9}, {%0,%1,%2,%3};"
                        : "+f"(c[m][nt][0]), "+f"(c[m][nt][1]),
                          "+f"(c[m][nt][2]), "+f"(c[m][nt][3])
                        : "r"(a[m][0]), "r"(a[m][1]), "r"(a[m][2]), "r"(a[m][3]),
                          "r"(b0), "r"(b1));
                }
            }
        }
        __syncthreads();
    }
#pragma unroll
    for (int m = 0; m < 2; m++) {
#pragma unroll
        for (int nt = 0; nt < 8; nt++) {
            int col = wn + nt * 8 + thr * 2;
            int gr0 = row0 + wm + m * 16 + grp;
            int gr1 = gr0 + 8;
            if constexpr (sizeof(OutT) == 2) {
                if (gr0 < M) {
                    __half2 v = __float22half2_rn(make_float2(c[m][nt][0], c[m][nt][1]));
                    *(__half2*)((__half*)Out + (size_t)gr0 * 128 + col) = v;
                }
                if (gr1 < M) {
                    __half2 v = __float22half2_rn(make_float2(c[m][nt][2], c[m][nt][3]));
                    *(__half2*)((__half*)Out + (size_t)gr1 * 128 + col) = v;
                }
            } else {
                if (gr0 < M)
                    *(float2*)((float*)Out + (size_t)gr0 * 128 + col) =
                        make_float2(c[m][nt][0], c[m][nt][1]);
                if (gr1 < M)
                    *(float2*)((float*)Out + (size_t)gr1 * 128 + col) =
                        make_float2(c[m][nt][2], c[m][nt][3]);
            }
        }
    }
}

// ---- CSR gather convs (fp16 features, MLP-4 pipelined): one warp per dst row ----

__global__ void k_conv1_gather(const __half* __restrict__ hin, const float* __restrict__ b,
                               __half* __restrict__ hout, int N) {
    int n = (blockIdx.x * blockDim.x + threadIdx.x) >> 5;
    int lane = threadIdx.x & 31;
    if (n >= N) return;
    float dn = g_disN[n];
    float4 a = h4f(((const uint2*)(hin + (size_t)n * HH))[lane]);
    float d2 = dn * dn;
    a.x *= d2; a.y *= d2; a.z *= d2; a.w *= d2;
    int e1 = g_rowptrN[n];
    int e0 = n ? g_rowptrN[n - 1] : 0;
    a = gather_nbrs(hin, g_ssN, e0, e1, dn, lane, a);
    float4 bv = ((const float4*)b)[lane];
    a.x = fmaxf(a.x + bv.x, 0.f);
    a.y = fmaxf(a.y + bv.y, 0.f);
    a.z = fmaxf(a.z + bv.z, 0.f);
    a.w = fmaxf(a.w + bv.w, 0.f);
    ((uint2*)(hout + (size_t)n * HH))[lane] = f4h(a);
}

// cluster mean pooling via membership CSR
__global__ void k_hp(const __half* __restrict__ h, float* __restrict__ hp, int C) {
    int c = (blockIdx.x * blockDim.x + threadIdx.x) >> 5;
    int lane = threadIdx.x & 31;
    if (c >= C) return;
    int m1 = g_rowptrCL[c];
    int m0 = c ? g_rowptrCL[c - 1] : 0;
    float4 a = make_float4(0.f, 0.f, 0.f, 0.f);
    int bmax = 0;
    int i = m0;
    for (; i + 4 <= m1; i += 4) {
        int n0 = g_memb[i], n1 = g_memb[i + 1], n2 = g_memb[i + 2], n3 = g_memb[i + 3];
        uint2 r0 = ((const uint2*)(h + (size_t)n0 * HH))[lane];
        uint2 r1 = ((const uint2*)(h + (size_t)n1 * HH))[lane];
        uint2 r2 = ((const uint2*)(h + (size_t)n2 * HH))[lane];
        uint2 r3 = ((const uint2*)(h + (size_t)n3 * HH))[lane];
        bmax = max(bmax, max(max(g_batch[n0], g_batch[n1]), max(g_batch[n2], g_batch[n3])));
        fma4(a, h4f(r0), 1.f); fma4(a, h4f(r1), 1.f);
        fma4(a, h4f(r2), 1.f); fma4(a, h4f(r3), 1.f);
    }
    for (; i < m1; i++) {
        int node = g_memb[i];
        bmax = max(bmax, g_batch[node]);
        fma4(a, h4f(((const uint2*)(h + (size_t)node * HH))[lane]), 1.f);
    }
    int cnt = m1 - m0;
    float sc = 1.0f / (float)(cnt > 0 ? cnt : 1);
    a.x *= sc; a.y *= sc; a.z *= sc; a.w *= sc;
    ((float4*)(hp + (size_t)c * HH))[lane] = a;
    if (lane == 0) {
        g_batchp[c] = bmax;
        atomicAdd(&P_CNTPG[bmax], 1);
    }
}

__global__ void k_convp_gather(const __half* __restrict__ hin, const float* __restrict__ b,
                               float* __restrict__ out, int C) {
    int n = (blockIdx.x * blockDim.x + threadIdx.x) >> 5;
    int lane = threadIdx.x & 31;
    if (n >= C) return;
    float dn = g_disP[n];
    float4 a = h4f(((const uint2*)(hin + (size_t)n * HH))[lane]);
    float d2 = dn * dn;
    a.x *= d2; a.y *= d2; a.z *= d2; a.w *= d2;
    int e1 = g_rowptrC[n];
    int e0 = n ? g_rowptrC[n - 1] : 0;
    a = gather_nbrs(hin, g_ssP, e0, e1, dn, lane, a);
    float4 bv = ((const float4*)b)[lane];
    a.x = fmaxf(a.x + bv.x, 0.f);
    a.y = fmaxf(a.y + bv.y, 0.f);
    a.z = fmaxf(a.z + bv.z, 0.f);
    a.w = fmaxf(a.w + bv.w, 0.f);
    ((float4*)(out + (size_t)n * HH))[lane] = a;
}

__global__ void k_convp_post(const __half* __restrict__ hin, const float* __restrict__ b,
                             int C) {
    int n = (blockIdx.x * blockDim.x + threadIdx.x) >> 5;
    int lane = threadIdx.x & 31;
    if (n >= C) return;
    float dn = g_disP[n];
    float4 a = h4f(((const uint2*)(hin + (size_t)n * HH))[lane]);
    float d2 = dn * dn;
    a.x *= d2; a.y *= d2; a.z *= d2; a.w *= d2;
    int e1 = g_rowptrC[n];
    int e0 = n ? g_rowptrC[n - 1] : 0;
    a = gather_nbrs(hin, g_ssP, e0, e1, dn, lane, a);
    float4 bv = ((const float4*)b)[lane];
    a.x = fmaxf(a.x + bv.x, 0.f);
    a.y = fmaxf(a.y + bv.y, 0.f);
    a.z = fmaxf(a.z + bv.z, 0.f);
    a.w = fmaxf(a.w + bv.w, 0.f);
    int g = g_batchp[n];
    red_add_v4(P_POSTSUM + (size_t)g * HH + lane * 4, a);
    int* pm = (int*)(P_POSTMAX + (size_t)g * HH + lane * 4);
    atomicMax(pm + 0, __float_as_int(a.x));
    atomicMax(pm + 1, __float_as_int(a.y));
    atomicMax(pm + 2, __float_as_int(a.z));
    atomicMax(pm + 3, __float_as_int(a.w));
}

// pre-pool partial mean/max over fp16 h (PPB blocks per graph)
__global__ void k_prepool(const __half* __restrict__ h, int N) {
    int g = blockIdx.x / PPB;
    int chunk = blockIdx.x % PPB;
    int j = threadIdx.x;  // 128
    int lo = 0, hi = N;
    while (lo < hi) { int m = (lo + hi) >> 1; if (g_batch[m] < g) lo = m + 1; else hi = m; }
    int s = lo;
    lo = s; hi = N;
    while (lo < hi) { int m = (lo + hi) >> 1; if (g_batch[m] < g + 1) lo = m + 1; else hi = m; }
    int e = lo;
    int len = e - s;
    int c0 = s + (int)((long long)len * chunk / PPB);
    int c1 = s + (int)((long long)len * (chunk + 1) / PPB);
    float sum = 0.f, mx = 0.f;
#pragma unroll 8
    for (int n = c0; n < c1; n++) {
        float v = __half2float(h[(size_t)n * HH + j]);
        sum += v;
        mx = fmaxf(mx, v);
    }
    if (c1 > c0) {
        red_add_f(P_PRESUM + g * HH + j, sum);
        atomicMax((int*)(P_PREMAX + g * HH + j), __float_as_int(mx));
    }
}

// final MLP + log_softmax (one block per graph)
__global__ void k_final(const float* __restrict__ l1w, const float* __restrict__ l1b,
                        const float* __restrict__ l2w, const float* __restrict__ l2b,
                        float* __restrict__ out, int N) {
    __shared__ float zs[512];
    __shared__ float ys[128];
    __shared__ float os[10];
    int g = blockIdx.x, j = threadIdx.x;
    int lo = 0, hi = N;
    while (lo < hi) { int m = (lo + hi) >> 1; if (g_batch[m] < g) lo = m + 1; else hi = m; }
    int s = lo;
    lo = s; hi = N;
    while (lo < hi) { int m = (lo + hi) >> 1; if (g_batch[m] < g + 1) lo = m + 1; else hi = m; }
    int cntN = lo - s;
    int cpg = P_CNTPG[g];
    zs[j]       = P_PRESUM[g * HH + j] / (float)(cntN > 0 ? cntN : 1);
    zs[128 + j] = P_PREMAX[g * HH + j];
    zs[256 + j] = P_POSTSUM[g * HH + j] / (float)(cpg > 0 ? cpg : 1);
    zs[384 + j] = P_POSTMAX[g * HH + j];
    __syncthreads();
    float acc = l1b[j];
#pragma unroll 8
    for (int k = 0; k < 512; k++) acc += zs[k] * l1w[k * 128 + j];
    ys[j] = fmaxf(acc, 0.f);
    __syncthreads();
    if (j < 10) {
        float a = l2b[j];
#pragma unroll 8
        for (int k = 0; k < 128; k++) a += ys[k] * l2w[k * 10 + j];
        os[j] = a;
    }
    __syncthreads();
    if (j < 10) {
        float m = os[0];
#pragma unroll
        for (int i = 1; i < 10; i++) m = fmaxf(m, os[i]);
        float ssum = 0.f;
#pragma unroll
        for (int i = 0; i < 10; i++) ssum += expf(os[i] - m);
        out[g * 10 + j] = os[j] - m - logf(ssum);
    }
}

// ---------------- host launcher ----------------
extern "C" void kernel_launch(void* const* d_in, const int* in_sizes, int n_in,
                              void* d_out, int out_size) {
    const float* x   = (const float*)d_in[0];
    const void*  ei  = d_in[1];
    const void*  ba  = d_in[2];
    const void*  cl  = d_in[3];
    const float* W1  = (const float*)d_in[6];
    const float* b1  = (const float*)d_in[7];
    const float* W2  = (const float*)d_in[8];
    const float* b2  = (const float*)d_in[9];
    const float* W3  = (const float*)d_in[10];
    const float* b3  = (const float*)d_in[11];
    const float* l1w = (const float*)d_in[12];
    const float* l1b = (const float*)d_in[13];
    const float* l2w = (const float*)d_in[14];
    const float* l2b = (const float*)d_in[15];
    float* out = (float*)d_out;

    int N = in_sizes[0] / HH;
    int E = in_sizes[1] / 2;
    int C = CC;
    (void)n_in; (void)out_size;

    void* p;
    cudaGetSymbolAddress(&p, g_h0h);      __half* h0h = (__half*)p;
    cudaGetSymbolAddress(&p, g_hh);       __half* hh  = (__half*)p;
    cudaGetSymbolAddress(&p, g_hw);       __half* hw  = (__half*)p;
    cudaGetSymbolAddress(&p, g_hp);       float* hp   = (float*)p;
    cudaGetSymbolAddress(&p, g_hp2);      float* hp2  = (float*)p;
    cudaGetSymbolAddress(&p, g_rowptrN);  int* rpN    = (int*)p;
    cudaGetSymbolAddress(&p, g_rowptrC);  int* rpC    = (int*)p;
    cudaGetSymbolAddress(&p, g_rowptrCL); int* rpCL   = (int*)p;
    cudaGetSymbolAddress(&p, g_auxN);     int* auxN   = (int*)p;
    cudaGetSymbolAddress(&p, g_auxC);     int* auxC   = (int*)p;
    cudaGetSymbolAddress(&p, g_auxCL);    int* auxCL  = (int*)p;
    cudaGetSymbolAddress(&p, g_zbuf);     unsigned int* zb = (unsigned int*)p;
    int* degN = (int*)(zb + OFF_DEGN);
    int* degP = (int*)(zb + OFF_DEGP);
    int* cntC = (int*)(zb + OFF_CNTC);

    const int T = 256;
    int ebl = (E + T - 1) / T;
    int nbl = (N + T - 1) / T;
    int cbl = (C + T - 1) / T;
    int nwb = (N + 7) / 8;
    int cwb = (C + 7) / 8;
    int nbN = (N + 1023) / 1024;
    int nbC = (C + 1023) / 1024;

    k_zero<<<512, T>>>(ei);
    k_prep_nodes<<<nbl, T>>>(cl, ba, N);
    k_prep_edges<<<ebl, T>>>(ei, E);
    k_dis<<<nbl, T>>>(N, C);

    // CSR builds (scans produce start offsets; k_place leaves end offsets)
    k_scan_block<<<nbN, 256>>>(degN, rpN, auxN, N);
    k_scan_aux<<<1, 1>>>(auxN, nbN);
    k_scan_add<<<nbl, T>>>(rpN, auxN, N, E);
    k_scan_block<<<nbC, 256>>>(degP, rpC, auxC, C);
    k_scan_aux<<<1, 1>>>(auxC, nbC);
    k_scan_add<<<cbl, T>>>(rpC, auxC, C, E);
    k_scan_block<<<nbC, 256>>>(cntC, rpCL, auxCL, C);
    k_scan_aux<<<1, 1>>>(auxCL, nbC);
    k_scan_add<<<cbl, T>>>(rpCL, auxCL, C, N);
    k_place<<<ebl, T>>>(E);
    k_place_nodes<<<nbl, T>>>(N);

    // conv1
    k_gemm_tc<__half><<<(N + 127) / 128, 256>>>(x, W1, h0h, N);
    k_conv1_gather<<<nwb, T>>>(h0h, b1, hh, N);

    // pre pooling + cluster mean (batch_p, CNTPG)
    k_prepool<<<GG * PPB, 128>>>(hh, N);
    k_hp<<<cwb, T>>>(hh, hp, C);

    // conv2
    k_gemm_tc<__half><<<(C + 127) / 128, 256>>>(hp, W2, hw, C);
    k_convp_gather<<<cwb, T>>>(hw, b2, hp2, C);

    // conv3 (fused post pooling)
    k_gemm_tc<__half><<<(C + 127) / 128, 256>>>(hp2, W3, hw, C);
    k_convp_post<<<cwb, T>>>(hw, b3, C);

    // MLP head + log_softmax
    k_final<<<GG, 128>>>(l1w, l1b, l2w, l2b, out, N);
}